// round 1
// baseline (speedup 1.0000x reference)
#include <cuda_runtime.h>
#include <math.h>

#define N0_ 60000
#define N1_ 15000
#define N2_ 3750
#define K_  32
#define P_  15

// ---------------- intermediate buffers (device globals; no allocations) ----------
__device__ __align__(16) float g_f1  [N0_*64];        // skip0
__device__ __align__(16) float g_f2  [N1_*64];
__device__ __align__(16) float g_f3  [N1_*128];       // skip1
__device__ __align__(16) float g_f4  [N2_*128];
__device__ __align__(16) float g_f5  [N2_*256];
__device__ __align__(16) float g_fk  [N1_*P_*64];     // 14.4M floats, reused by all gathers
__device__ __align__(16) float g_u1in[N1_*384];
__device__ __align__(16) float g_fu1 [N1_*128];
__device__ __align__(16) float g_u2in[N0_*192];
__device__ __align__(16) float g_ff  [N0_*32];
__device__ int g_gmax;

// ---------------- layer 1: KPConv with Cin=1, Cout=64, fully fused ---------------
__global__ void conv1_kernel(const float* __restrict__ pts, const int* __restrict__ neigh,
                             const float* __restrict__ feats, const float* __restrict__ kp,
                             const float* __restrict__ W1, float* __restrict__ out)
{
    const float extent = 0.5f;
    __shared__ float sdiff[K_*3];
    __shared__ float sfeat[K_];
    __shared__ float sinfl[K_*P_];
    __shared__ float sfk[P_];
    int n = blockIdx.x;
    int t = threadIdx.x; // 64 threads
    float qx = pts[n*3+0], qy = pts[n*3+1], qz = pts[n*3+2];
    if (t < K_) {
        int idx = neigh[n*K_+t];
        sdiff[t*3+0] = pts[idx*3+0]-qx;
        sdiff[t*3+1] = pts[idx*3+1]-qy;
        sdiff[t*3+2] = pts[idx*3+2]-qz;
        sfeat[t] = feats[idx];
    }
    __syncthreads();
    for (int i = t; i < K_*P_; i += 64) {
        int k = i / P_, p = i % P_;
        float dx = sdiff[k*3+0] - kp[p*3+0]*extent;
        float dy = sdiff[k*3+1] - kp[p*3+1]*extent;
        float dz = sdiff[k*3+2] - kp[p*3+2]*extent;
        float dist = sqrtf(dx*dx+dy*dy+dz*dz);
        sinfl[i] = fmaxf(0.f, 1.f - dist/extent);
    }
    __syncthreads();
    if (t < P_) {
        float acc = 0.f;
        #pragma unroll
        for (int k = 0; k < K_; k++) acc += sinfl[k*P_+t]*sfeat[k];
        sfk[t] = acc;
    }
    __syncthreads();
    float acc = 0.f;
    #pragma unroll
    for (int p = 0; p < P_; p++) acc += sfk[p]*W1[p*64+t];
    out[n*64+t] = acc > 0.f ? acc : 0.1f*acc;
}

// ---------------- gather phase: fk[n, p*CIN+c] = sum_k infl[n,k,p]*feat[idx,c] ----
template<int CIN>
__global__ void gather_fk_kernel(const float* __restrict__ qpts, const float* __restrict__ spts,
                                 const int* __restrict__ neigh, const float* __restrict__ feats,
                                 const float* __restrict__ kp, float extent, float* __restrict__ fk)
{
    __shared__ float sdiff[K_*3];
    __shared__ int   sidx[K_];
    __shared__ float sinfl[K_*P_];
    int n = blockIdx.x;
    int t = threadIdx.x; // CIN threads
    float qx = qpts[n*3+0], qy = qpts[n*3+1], qz = qpts[n*3+2];
    if (t < K_) {
        int idx = neigh[n*K_+t];
        sidx[t] = idx;
        sdiff[t*3+0] = spts[idx*3+0]-qx;
        sdiff[t*3+1] = spts[idx*3+1]-qy;
        sdiff[t*3+2] = spts[idx*3+2]-qz;
    }
    __syncthreads();
    for (int i = t; i < K_*P_; i += CIN) {
        int k = i / P_, p = i % P_;
        float dx = sdiff[k*3+0] - kp[p*3+0]*extent;
        float dy = sdiff[k*3+1] - kp[p*3+1]*extent;
        float dz = sdiff[k*3+2] - kp[p*3+2]*extent;
        float dist = sqrtf(dx*dx+dy*dy+dz*dz);
        sinfl[i] = fmaxf(0.f, 1.f - dist/extent);
    }
    __syncthreads();
    float acc[P_];
    #pragma unroll
    for (int p = 0; p < P_; p++) acc[p] = 0.f;
    #pragma unroll 4
    for (int k = 0; k < K_; k++) {
        float f = feats[(size_t)sidx[k]*CIN + t];
        #pragma unroll
        for (int p = 0; p < P_; p++) acc[p] += sinfl[k*P_+p]*f;
    }
    size_t base = (size_t)n*(P_*CIN) + t;
    #pragma unroll
    for (int p = 0; p < P_; p++) fk[base + (size_t)p*CIN] = acc[p];
}

// ---------------- fp32 tiled GEMM: C[M,N] = act(A[M,Kd] @ B[Kd,N]) ----------------
// BM=64, BN=64, BK=16, 256 threads, 4x4 microtile. Kd % 16 == 0, N % 4 == 0.
template<bool LEAKY>
__global__ __launch_bounds__(256)
void gemm_kernel(const float* __restrict__ A, const float* __restrict__ B,
                 float* __restrict__ C, int M, int N, int Kd)
{
    __shared__ float As[16][64+1];
    __shared__ float Bs[16][64];
    int bm = blockIdx.y*64, bn = blockIdx.x*64;
    int tid = threadIdx.x;
    int tx = tid & 15, ty = tid >> 4;
    float acc[4][4];
    #pragma unroll
    for (int i=0;i<4;i++) { acc[i][0]=0.f;acc[i][1]=0.f;acc[i][2]=0.f;acc[i][3]=0.f; }
    int aRow = tid >> 2;           // 0..63 m-in-tile
    int aCol = (tid & 3) * 4;      // k offset (float4)
    int bRow = tid >> 4;           // 0..15 k-in-tile
    int bCol = (tid & 15) * 4;     // n offset (float4)
    bool aValid = (bm + aRow) < M;
    bool bValid = (bn + bCol) < N;
    for (int k0 = 0; k0 < Kd; k0 += 16) {
        float4 av = make_float4(0.f,0.f,0.f,0.f);
        if (aValid) av = *(const float4*)&A[(size_t)(bm+aRow)*Kd + k0 + aCol];
        As[aCol+0][aRow]=av.x; As[aCol+1][aRow]=av.y;
        As[aCol+2][aRow]=av.z; As[aCol+3][aRow]=av.w;
        float4 bv = make_float4(0.f,0.f,0.f,0.f);
        if (bValid) bv = *(const float4*)&B[(size_t)(k0+bRow)*N + bn + bCol];
        *(float4*)&Bs[bRow][bCol] = bv;
        __syncthreads();
        #pragma unroll
        for (int kk = 0; kk < 16; kk++) {
            float a[4], b[4];
            #pragma unroll
            for (int i=0;i<4;i++) a[i] = As[kk][ty*4+i];
            #pragma unroll
            for (int j=0;j<4;j++) b[j] = Bs[kk][tx*4+j];
            #pragma unroll
            for (int i=0;i<4;i++)
                #pragma unroll
                for (int j=0;j<4;j++)
                    acc[i][j] += a[i]*b[j];
        }
        __syncthreads();
    }
    #pragma unroll
    for (int i=0;i<4;i++) {
        int m = bm + ty*4 + i;
        if (m >= M) continue;
        #pragma unroll
        for (int j=0;j<4;j++) {
            int nn = bn + tx*4 + j;
            if (nn >= N) continue;
            float v = acc[i][j];
            if (LEAKY) v = v > 0.f ? v : 0.1f*v;
            C[(size_t)m*N + nn] = v;
        }
    }
}

// ---------------- decoder concat (nearest upsample + skip) ------------------------
__global__ void concat_kernel(const float* __restrict__ up_f, const int* __restrict__ up_idx,
                              const float* __restrict__ skip, float* __restrict__ out,
                              int n_rows, int c_up, int c_skip)
{
    int cw = c_up + c_skip;
    int total = n_rows * cw;
    for (int j = blockIdx.x*blockDim.x + threadIdx.x; j < total; j += gridDim.x*blockDim.x) {
        int n = j / cw, col = j - n*cw;
        out[j] = (col < c_up) ? up_f[(size_t)up_idx[n]*c_up + col]
                              : skip[(size_t)n*c_skip + col - c_up];
    }
}

// ---------------- detection head --------------------------------------------------
__global__ void init_gmax_kernel() { g_gmax = 0; }   // bits of +0.0f

__global__ void reduce_max_kernel(const float* __restrict__ x, int n)
{
    float m = 0.f;  // jnp.max includes the appended zero row -> clamp at 0
    for (int i = blockIdx.x*blockDim.x + threadIdx.x; i < n; i += gridDim.x*blockDim.x)
        m = fmaxf(m, x[i]);
    #pragma unroll
    for (int o = 16; o; o >>= 1) m = fmaxf(m, __shfl_xor_sync(0xffffffffu, m, o));
    if ((threadIdx.x & 31) == 0) atomicMax(&g_gmax, __float_as_int(m));  // m>=0: bits monotone
}

__global__ void scores_kernel(const int* __restrict__ neigh, const float* __restrict__ ff,
                              float* __restrict__ out_fnorm, float* __restrict__ out_scores)
{
    int warp = (blockIdx.x*blockDim.x + threadIdx.x) >> 5;
    int lane = threadIdx.x & 31;
    if (warp >= N0_) return;
    float fraw = ff[(size_t)warp*32 + lane];
    // fnorm (scale-invariant; use raw features)
    float s2 = fraw*fraw;
    #pragma unroll
    for (int o = 16; o; o >>= 1) s2 += __shfl_xor_sync(0xffffffffu, s2, o);
    float nrm = fmaxf(sqrtf(s2), 1e-12f);
    out_fnorm[(size_t)warp*32 + lane] = fraw / nrm;

    float gmax = __int_as_float(g_gmax);
    float denom = gmax + 1e-6f;
    float f = fraw / denom;
    int myidx = neigh[(size_t)warp*32 + lane];
    float sumf = 0.f, nmax = -1e30f; int nnum = 0;
    for (int k = 0; k < K_; k++) {
        int idx = __shfl_sync(0xffffffffu, myidx, k);
        float nf = ff[(size_t)idx*32 + lane] / denom;
        float rs = nf;
        #pragma unroll
        for (int o = 16; o; o >>= 1) rs += __shfl_xor_sync(0xffffffffu, rs, o);
        sumf += nf;
        nmax = fmaxf(nmax, nf);
        nnum += (rs != 0.f);
    }
    if (nnum < 1) nnum = 1;
    float mean = sumf / (float)nnum;
    float x = f - mean;
    float lms = fmaxf(x, 0.f) + log1pf(expf(-fabsf(x)));   // stable softplus
    float dmax = f;
    #pragma unroll
    for (int o = 16; o; o >>= 1) dmax = fmaxf(dmax, __shfl_xor_sync(0xffffffffu, dmax, o));
    float alls = lms * f / (1e-6f + dmax);
    float sc = alls;
    #pragma unroll
    for (int o = 16; o; o >>= 1) sc = fmaxf(sc, __shfl_xor_sync(0xffffffffu, sc, o));
    float det = (f == nmax) ? 1.f : 0.f;
    #pragma unroll
    for (int o = 16; o; o >>= 1) det = fmaxf(det, __shfl_xor_sync(0xffffffffu, det, o));
    if (lane == 0) out_scores[warp] = sc * det;
}

// ---------------- launch ----------------------------------------------------------
static inline dim3 ggrid(int M, int N) { return dim3((N+63)/64, (M+63)/64); }

extern "C" void kernel_launch(void* const* d_in, const int* in_sizes, int n_in,
                              void* d_out, int out_size)
{
    const float* features   = (const float*)d_in[0];
    const float* points0    = (const float*)d_in[1];
    const float* points1    = (const float*)d_in[2];
    const float* points2    = (const float*)d_in[3];
    const int*   neighbors0 = (const int*)d_in[4];
    const int*   neighbors1 = (const int*)d_in[5];
    const int*   neighbors2 = (const int*)d_in[6];
    const int*   pools0     = (const int*)d_in[7];
    const int*   pools1     = (const int*)d_in[8];
    const int*   upsamples0 = (const int*)d_in[9];
    const int*   upsamples1 = (const int*)d_in[10];
    const float* kpoints    = (const float*)d_in[11];
    const float* W1  = (const float*)d_in[12];
    const float* W2  = (const float*)d_in[13];
    const float* W3  = (const float*)d_in[14];
    const float* W4  = (const float*)d_in[15];
    const float* W5  = (const float*)d_in[16];
    const float* Wu1 = (const float*)d_in[17];
    const float* Wu2 = (const float*)d_in[18];
    float* out = (float*)d_out;

    float *f1,*f2,*f3,*f4,*f5,*fk,*u1in,*fu1,*u2in,*ff;
    cudaGetSymbolAddress((void**)&f1,  g_f1);
    cudaGetSymbolAddress((void**)&f2,  g_f2);
    cudaGetSymbolAddress((void**)&f3,  g_f3);
    cudaGetSymbolAddress((void**)&f4,  g_f4);
    cudaGetSymbolAddress((void**)&f5,  g_f5);
    cudaGetSymbolAddress((void**)&fk,  g_fk);
    cudaGetSymbolAddress((void**)&u1in,g_u1in);
    cudaGetSymbolAddress((void**)&fu1, g_fu1);
    cudaGetSymbolAddress((void**)&u2in,g_u2in);
    cudaGetSymbolAddress((void**)&ff,  g_ff);

    // ---- encoder ----
    conv1_kernel<<<N0_, 64>>>(points0, neighbors0, features, kpoints, W1, f1);

    gather_fk_kernel<64><<<N1_, 64>>>(points1, points0, pools0, f1, kpoints, 0.5f, fk);
    gemm_kernel<true><<<ggrid(N1_,64), 256>>>(fk, W2, f2, N1_, 64, 15*64);

    gather_fk_kernel<64><<<N1_, 64>>>(points1, points1, neighbors1, f2, kpoints, 1.0f, fk);
    gemm_kernel<true><<<ggrid(N1_,128), 256>>>(fk, W3, f3, N1_, 128, 15*64);

    gather_fk_kernel<128><<<N2_, 128>>>(points2, points1, pools1, f3, kpoints, 1.0f, fk);
    gemm_kernel<true><<<ggrid(N2_,128), 256>>>(fk, W4, f4, N2_, 128, 15*128);

    gather_fk_kernel<128><<<N2_, 128>>>(points2, points2, neighbors2, f4, kpoints, 2.0f, fk);
    gemm_kernel<true><<<ggrid(N2_,256), 256>>>(fk, W5, f5, N2_, 256, 15*128);

    // ---- decoder ----
    concat_kernel<<<1024, 256>>>(f5, upsamples1, f3, u1in, N1_, 256, 128);
    gemm_kernel<true><<<ggrid(N1_,128), 256>>>(u1in, Wu1, fu1, N1_, 128, 384);

    concat_kernel<<<2048, 256>>>(fu1, upsamples0, f1, u2in, N0_, 128, 64);
    gemm_kernel<false><<<ggrid(N0_,32), 256>>>(u2in, Wu2, ff, N0_, 32, 192);

    // ---- detection head + outputs ----
    init_gmax_kernel<<<1,1>>>();
    reduce_max_kernel<<<256, 256>>>(ff, N0_*32);
    scores_kernel<<<(N0_ + 7)/8, 256>>>(neighbors0, ff, out, out + (size_t)N0_*32);
}

// round 2
// speedup vs baseline: 1.6018x; 1.6018x over previous
#include <cuda_runtime.h>
#include <math.h>
#include <stdint.h>

#define N0_ 60000
#define N1_ 15000
#define N2_ 3750
#define K_  32
#define P_  15

// ---------------- intermediate buffers (device globals; no allocations) ----------
__device__ __align__(16) float g_f1  [N0_*64];        // skip0
__device__ __align__(16) float g_f2  [N1_*64];
__device__ __align__(16) float g_f3  [N1_*128];       // skip1
__device__ __align__(16) float g_f4  [N2_*128];
__device__ __align__(16) float g_f5  [N2_*256];
__device__ __align__(16) float g_fk  [N1_*P_*64];     // reused by all gathers
__device__ __align__(16) float g_u1in[N1_*384];
__device__ __align__(16) float g_fu1 [N1_*128];
__device__ __align__(16) float g_u2in[N0_*192];
__device__ __align__(16) float g_ff  [N0_*32];
__device__ int g_gmax;

// ---------------- layer 1: KPConv with Cin=1, Cout=64, fully fused ---------------
__global__ void conv1_kernel(const float* __restrict__ pts, const int* __restrict__ neigh,
                             const float* __restrict__ feats, const float* __restrict__ kp,
                             const float* __restrict__ W1, float* __restrict__ out)
{
    const float extent = 0.5f;
    __shared__ float sdiff[K_*3];
    __shared__ float sfeat[K_];
    __shared__ float sinfl[K_*P_];
    __shared__ float sfk[P_];
    int n = blockIdx.x;
    int t = threadIdx.x; // 64 threads
    float qx = pts[n*3+0], qy = pts[n*3+1], qz = pts[n*3+2];
    if (t < K_) {
        int idx = neigh[n*K_+t];
        sdiff[t*3+0] = pts[idx*3+0]-qx;
        sdiff[t*3+1] = pts[idx*3+1]-qy;
        sdiff[t*3+2] = pts[idx*3+2]-qz;
        sfeat[t] = feats[idx];
    }
    __syncthreads();
    for (int i = t; i < K_*P_; i += 64) {
        int k = i / P_, p = i % P_;
        float dx = sdiff[k*3+0] - kp[p*3+0]*extent;
        float dy = sdiff[k*3+1] - kp[p*3+1]*extent;
        float dz = sdiff[k*3+2] - kp[p*3+2]*extent;
        float dist = sqrtf(dx*dx+dy*dy+dz*dz);
        sinfl[i] = fmaxf(0.f, 1.f - dist/extent);
    }
    __syncthreads();
    if (t < P_) {
        float acc = 0.f;
        #pragma unroll
        for (int k = 0; k < K_; k++) acc += sinfl[k*P_+t]*sfeat[k];
        sfk[t] = acc;
    }
    __syncthreads();
    float acc = 0.f;
    #pragma unroll
    for (int p = 0; p < P_; p++) acc += sfk[p]*W1[p*64+t];
    out[n*64+t] = acc > 0.f ? acc : 0.1f*acc;
}

// ---------------- gather phase: fk[n, p*CIN+c] = sum_k infl[n,k,p]*feat[idx,c] ----
template<int CIN>
__global__ void gather_fk_kernel(const float* __restrict__ qpts, const float* __restrict__ spts,
                                 const int* __restrict__ neigh, const float* __restrict__ feats,
                                 const float* __restrict__ kp, float extent, float* __restrict__ fk)
{
    __shared__ float sdiff[K_*3];
    __shared__ int   sidx[K_];
    __shared__ float sinfl[K_*P_];
    int n = blockIdx.x;
    int t = threadIdx.x; // CIN threads
    float qx = qpts[n*3+0], qy = qpts[n*3+1], qz = qpts[n*3+2];
    if (t < K_) {
        int idx = neigh[n*K_+t];
        sidx[t] = idx;
        sdiff[t*3+0] = spts[idx*3+0]-qx;
        sdiff[t*3+1] = spts[idx*3+1]-qy;
        sdiff[t*3+2] = spts[idx*3+2]-qz;
    }
    __syncthreads();
    for (int i = t; i < K_*P_; i += CIN) {
        int k = i / P_, p = i % P_;
        float dx = sdiff[k*3+0] - kp[p*3+0]*extent;
        float dy = sdiff[k*3+1] - kp[p*3+1]*extent;
        float dz = sdiff[k*3+2] - kp[p*3+2]*extent;
        float dist = sqrtf(dx*dx+dy*dy+dz*dz);
        sinfl[i] = fmaxf(0.f, 1.f - dist/extent);
    }
    __syncthreads();
    float acc[P_];
    #pragma unroll
    for (int p = 0; p < P_; p++) acc[p] = 0.f;
    #pragma unroll 4
    for (int k = 0; k < K_; k++) {
        float f = feats[(size_t)sidx[k]*CIN + t];
        #pragma unroll
        for (int p = 0; p < P_; p++) acc[p] += sinfl[k*P_+p]*f;
    }
    size_t base = (size_t)n*(P_*CIN) + t;
    #pragma unroll
    for (int p = 0; p < P_; p++) fk[base + (size_t)p*CIN] = acc[p];
}

// ================= tf32 tensor-core GEMM =========================================
// C[M,N] = act(A[M,Kd] @ B[Kd,N]).  Kd % 16 == 0, N % 32 == 0.
// BM = MF*64 (MF=2 -> 128), BN = 64, BK = 16. 256 threads = 8 warps (4 M x 2 N).
// Warp tile: (MF*16) x 32. mma.m16n8k8 tf32, cvt.rna rounding, 2-stage cp.async.

__device__ __forceinline__ uint32_t f2tf32(float x) {
    uint32_t u;
    asm("cvt.rna.tf32.f32 %0, %1;" : "=r"(u) : "f"(x));
    return u;
}

__device__ __forceinline__ void cpasync16(uint32_t dst, const void* src, bool valid) {
    int sz = valid ? 16 : 0;
    asm volatile("cp.async.cg.shared.global [%0], [%1], 16, %2;\n"
                 :: "r"(dst), "l"(src), "r"(sz));
}

template<int MF, bool LEAKY>
__global__ __launch_bounds__(256)
void gemm_tc(const float* __restrict__ A, const float* __restrict__ B,
             float* __restrict__ C, int M, int N, int Kd)
{
    constexpr int BM = MF * 64;
    __shared__ float As[2][BM][20];   // [m][k], pad 16->20 : conflict-free frag loads
    __shared__ float Bs[2][16][68];   // [k][n], pad 64->68

    const int bm = blockIdx.y * BM, bn = blockIdx.x * 64;
    const int tid  = threadIdx.x;
    const int warp = tid >> 5, lane = tid & 31;
    const int wm = warp >> 1, wn = warp & 1;
    const int g  = lane >> 2, tg = lane & 3;

    float c[MF][4][4];
    #pragma unroll
    for (int i = 0; i < MF; i++)
        #pragma unroll
        for (int j = 0; j < 4; j++) {
            c[i][j][0]=0.f; c[i][j][1]=0.f; c[i][j][2]=0.f; c[i][j][3]=0.f;
        }

    // global -> shared load assignment
    const int ar  = tid >> 2;          // 0..63 (row in tile, + i*64)
    const int ac  = (tid & 3) * 4;     // k offset (float4)
    const int bk  = tid >> 4;          // 0..15
    const int bn4 = (tid & 15) * 4;    // 0..60
    const bool bval = (bn + bn4) < N;

    const int nk = Kd >> 4;

    // ---- stage issue ----
    auto issue = [&](int s, int k0) {
        #pragma unroll
        for (int i = 0; i < MF; i++) {
            int r = ar + i * 64;
            bool v = (bm + r) < M;
            const float* src = v ? (A + (size_t)(bm + r) * Kd + k0 + ac) : A;
            cpasync16((uint32_t)__cvta_generic_to_shared(&As[s][r][ac]), src, v);
        }
        const float* srcb = bval ? (B + (size_t)(k0 + bk) * N + bn + bn4) : B;
        cpasync16((uint32_t)__cvta_generic_to_shared(&Bs[s][bk][bn4]), srcb, bval);
        asm volatile("cp.async.commit_group;\n");
    };

    auto compute = [&](int s) {
        #pragma unroll
        for (int k0 = 0; k0 < 16; k0 += 8) {
            uint32_t a[MF][4], bf[4][2];
            #pragma unroll
            for (int i = 0; i < MF; i++) {
                int r = wm * MF * 16 + i * 16 + g;
                a[i][0] = f2tf32(As[s][r    ][k0 + tg    ]);
                a[i][1] = f2tf32(As[s][r + 8][k0 + tg    ]);
                a[i][2] = f2tf32(As[s][r    ][k0 + tg + 4]);
                a[i][3] = f2tf32(As[s][r + 8][k0 + tg + 4]);
            }
            #pragma unroll
            for (int j = 0; j < 4; j++) {
                int col = wn * 32 + j * 8 + g;
                bf[j][0] = f2tf32(Bs[s][k0 + tg    ][col]);
                bf[j][1] = f2tf32(Bs[s][k0 + tg + 4][col]);
            }
            #pragma unroll
            for (int i = 0; i < MF; i++)
                #pragma unroll
                for (int j = 0; j < 4; j++)
                    asm volatile(
                        "mma.sync.aligned.m16n8k8.row.col.f32.tf32.tf32.f32 "
                        "{%0,%1,%2,%3},{%4,%5,%6,%7},{%8,%9},{%0,%1,%2,%3};\n"
                        : "+f"(c[i][j][0]), "+f"(c[i][j][1]),
                          "+f"(c[i][j][2]), "+f"(c[i][j][3])
                        : "r"(a[i][0]), "r"(a[i][1]), "r"(a[i][2]), "r"(a[i][3]),
                          "r"(bf[j][0]), "r"(bf[j][1]));
        }
    };

    issue(0, 0);
    for (int kt = 0; kt < nk; kt++) {
        if (kt + 1 < nk) {
            issue((kt + 1) & 1, (kt + 1) << 4);
            asm volatile("cp.async.wait_group 1;\n");
        } else {
            asm volatile("cp.async.wait_group 0;\n");
        }
        __syncthreads();
        compute(kt & 1);
        __syncthreads();
    }

    // ---- store with activation ----
    #pragma unroll
    for (int i = 0; i < MF; i++) {
        int r0 = bm + wm * MF * 16 + i * 16 + g;
        #pragma unroll
        for (int j = 0; j < 4; j++) {
            int col = bn + wn * 32 + j * 8 + 2 * tg;
            if (col < N) {
                if (r0 < M) {
                    float v0 = c[i][j][0], v1 = c[i][j][1];
                    if (LEAKY) { v0 = v0 > 0.f ? v0 : 0.1f*v0; v1 = v1 > 0.f ? v1 : 0.1f*v1; }
                    C[(size_t)r0 * N + col]     = v0;
                    C[(size_t)r0 * N + col + 1] = v1;
                }
                if (r0 + 8 < M) {
                    float v2 = c[i][j][2], v3 = c[i][j][3];
                    if (LEAKY) { v2 = v2 > 0.f ? v2 : 0.1f*v2; v3 = v3 > 0.f ? v3 : 0.1f*v3; }
                    C[(size_t)(r0 + 8) * N + col]     = v2;
                    C[(size_t)(r0 + 8) * N + col + 1] = v3;
                }
            }
        }
    }
}

// ---------------- decoder concat (nearest upsample + skip) ------------------------
__global__ void concat_kernel(const float* __restrict__ up_f, const int* __restrict__ up_idx,
                              const float* __restrict__ skip, float* __restrict__ out,
                              int n_rows, int c_up, int c_skip)
{
    int cw = c_up + c_skip;
    int total = n_rows * cw;
    for (int j = blockIdx.x*blockDim.x + threadIdx.x; j < total; j += gridDim.x*blockDim.x) {
        int n = j / cw, col = j - n*cw;
        out[j] = (col < c_up) ? up_f[(size_t)up_idx[n]*c_up + col]
                              : skip[(size_t)n*c_skip + col - c_up];
    }
}

// ---------------- detection head --------------------------------------------------
__global__ void init_gmax_kernel() { g_gmax = 0; }

__global__ void reduce_max_kernel(const float* __restrict__ x, int n)
{
    float m = 0.f;
    for (int i = blockIdx.x*blockDim.x + threadIdx.x; i < n; i += gridDim.x*blockDim.x)
        m = fmaxf(m, x[i]);
    #pragma unroll
    for (int o = 16; o; o >>= 1) m = fmaxf(m, __shfl_xor_sync(0xffffffffu, m, o));
    if ((threadIdx.x & 31) == 0) atomicMax(&g_gmax, __float_as_int(m));
}

__global__ void scores_kernel(const int* __restrict__ neigh, const float* __restrict__ ff,
                              float* __restrict__ out_fnorm, float* __restrict__ out_scores)
{
    int warp = (blockIdx.x*blockDim.x + threadIdx.x) >> 5;
    int lane = threadIdx.x & 31;
    if (warp >= N0_) return;
    float fraw = ff[(size_t)warp*32 + lane];
    float s2 = fraw*fraw;
    #pragma unroll
    for (int o = 16; o; o >>= 1) s2 += __shfl_xor_sync(0xffffffffu, s2, o);
    float nrm = fmaxf(sqrtf(s2), 1e-12f);
    out_fnorm[(size_t)warp*32 + lane] = fraw / nrm;

    float gmax = __int_as_float(g_gmax);
    float denom = gmax + 1e-6f;
    float f = fraw / denom;
    int myidx = neigh[(size_t)warp*32 + lane];
    float sumf = 0.f, nmax = -1e30f; int nnum = 0;
    for (int k = 0; k < K_; k++) {
        int idx = __shfl_sync(0xffffffffu, myidx, k);
        float nf = ff[(size_t)idx*32 + lane] / denom;
        float rs = nf;
        #pragma unroll
        for (int o = 16; o; o >>= 1) rs += __shfl_xor_sync(0xffffffffu, rs, o);
        sumf += nf;
        nmax = fmaxf(nmax, nf);
        nnum += (rs != 0.f);
    }
    if (nnum < 1) nnum = 1;
    float mean = sumf / (float)nnum;
    float x = f - mean;
    float lms = fmaxf(x, 0.f) + log1pf(expf(-fabsf(x)));
    float dmax = f;
    #pragma unroll
    for (int o = 16; o; o >>= 1) dmax = fmaxf(dmax, __shfl_xor_sync(0xffffffffu, dmax, o));
    float alls = lms * f / (1e-6f + dmax);
    float sc = alls;
    #pragma unroll
    for (int o = 16; o; o >>= 1) sc = fmaxf(sc, __shfl_xor_sync(0xffffffffu, sc, o));
    float det = (f == nmax) ? 1.f : 0.f;
    #pragma unroll
    for (int o = 16; o; o >>= 1) det = fmaxf(det, __shfl_xor_sync(0xffffffffu, det, o));
    if (lane == 0) out_scores[warp] = sc * det;
}

// ---------------- launch ----------------------------------------------------------
extern "C" void kernel_launch(void* const* d_in, const int* in_sizes, int n_in,
                              void* d_out, int out_size)
{
    const float* features   = (const float*)d_in[0];
    const float* points0    = (const float*)d_in[1];
    const float* points1    = (const float*)d_in[2];
    const float* points2    = (const float*)d_in[3];
    const int*   neighbors0 = (const int*)d_in[4];
    const int*   neighbors1 = (const int*)d_in[5];
    const int*   neighbors2 = (const int*)d_in[6];
    const int*   pools0     = (const int*)d_in[7];
    const int*   pools1     = (const int*)d_in[8];
    const int*   upsamples0 = (const int*)d_in[9];
    const int*   upsamples1 = (const int*)d_in[10];
    const float* kpoints    = (const float*)d_in[11];
    const float* W1  = (const float*)d_in[12];
    const float* W2  = (const float*)d_in[13];
    const float* W3  = (const float*)d_in[14];
    const float* W4  = (const float*)d_in[15];
    const float* W5  = (const float*)d_in[16];
    const float* Wu1 = (const float*)d_in[17];
    const float* Wu2 = (const float*)d_in[18];
    float* out = (float*)d_out;

    float *f1,*f2,*f3,*f4,*f5,*fk,*u1in,*fu1,*u2in,*ff;
    cudaGetSymbolAddress((void**)&f1,  g_f1);
    cudaGetSymbolAddress((void**)&f2,  g_f2);
    cudaGetSymbolAddress((void**)&f3,  g_f3);
    cudaGetSymbolAddress((void**)&f4,  g_f4);
    cudaGetSymbolAddress((void**)&f5,  g_f5);
    cudaGetSymbolAddress((void**)&fk,  g_fk);
    cudaGetSymbolAddress((void**)&u1in,g_u1in);
    cudaGetSymbolAddress((void**)&fu1, g_fu1);
    cudaGetSymbolAddress((void**)&u2in,g_u2in);
    cudaGetSymbolAddress((void**)&ff,  g_ff);

    // ---- encoder ----
    conv1_kernel<<<N0_, 64>>>(points0, neighbors0, features, kpoints, W1, f1);

    gather_fk_kernel<64><<<N1_, 64>>>(points1, points0, pools0, f1, kpoints, 0.5f, fk);
    gemm_tc<2,true><<<dim3(1, (N1_+127)/128), 256>>>(fk, W2, f2, N1_, 64, 15*64);

    gather_fk_kernel<64><<<N1_, 64>>>(points1, points1, neighbors1, f2, kpoints, 1.0f, fk);
    gemm_tc<2,true><<<dim3(2, (N1_+127)/128), 256>>>(fk, W3, f3, N1_, 128, 15*64);

    gather_fk_kernel<128><<<N2_, 128>>>(points2, points1, pools1, f3, kpoints, 1.0f, fk);
    gemm_tc<1,true><<<dim3(2, (N2_+63)/64), 256>>>(fk, W4, f4, N2_, 128, 15*128);

    gather_fk_kernel<128><<<N2_, 128>>>(points2, points2, neighbors2, f4, kpoints, 2.0f, fk);
    gemm_tc<1,true><<<dim3(4, (N2_+63)/64), 256>>>(fk, W5, f5, N2_, 256, 15*128);

    // ---- decoder ----
    concat_kernel<<<1024, 256>>>(f5, upsamples1, f3, u1in, N1_, 256, 128);
    gemm_tc<2,true><<<dim3(2, (N1_+127)/128), 256>>>(u1in, Wu1, fu1, N1_, 128, 384);

    concat_kernel<<<2048, 256>>>(fu1, upsamples0, f1, u2in, N0_, 128, 64);
    gemm_tc<2,false><<<dim3(1, (N0_+127)/128), 256>>>(u2in, Wu2, ff, N0_, 32, 192);

    // ---- detection head + outputs ----
    init_gmax_kernel<<<1,1>>>();
    reduce_max_kernel<<<256, 256>>>(ff, N0_*32);
    scores_kernel<<<(N0_ + 7)/8, 256>>>(neighbors0, ff, out, out + (size_t)N0_*32);
}

// round 3
// speedup vs baseline: 1.8428x; 1.1504x over previous
#include <cuda_runtime.h>
#include <math.h>
#include <stdint.h>

#define N0_ 60000
#define N1_ 15000
#define N2_ 3750
#define K_  32
#define P_  15

// ---------------- intermediate buffers (device globals; no allocations) ----------
__device__ __align__(16) float g_f1  [N0_*64];        // skip0
__device__ __align__(16) float g_f2  [N1_*64];
__device__ __align__(16) float g_f3  [N1_*128];       // skip1
__device__ __align__(16) float g_f4  [N2_*128];
__device__ __align__(16) float g_f5  [N2_*256];
__device__ __align__(16) float g_fk  [N1_*P_*64];     // reused by all gathers
__device__ __align__(16) float g_fu1 [N1_*128];
__device__ __align__(16) float g_ff  [N0_*32];
__device__ float g_rowsum[N0_];
__device__ int g_gmax;

// ---------------- layer 1: KPConv Cin=1 Cout=64, 4 points / 256-thread block -----
__global__ __launch_bounds__(256)
void conv1_kernel(const float* __restrict__ pts, const int* __restrict__ neigh,
                  const float* __restrict__ feats, const float* __restrict__ kp,
                  const float* __restrict__ W1, float* __restrict__ out)
{
    const float extent = 0.5f;
    __shared__ float sdiff[4][K_][3];
    __shared__ float sfeat[4][K_];
    __shared__ float sinfl[4][K_*P_];
    __shared__ float sfk[4][P_];
    int pt = threadIdx.x >> 6;         // 0..3
    int t  = threadIdx.x & 63;
    int n  = blockIdx.x * 4 + pt;
    if (t < K_) {
        int idx = neigh[n*K_+t];
        float qx = pts[n*3+0], qy = pts[n*3+1], qz = pts[n*3+2];
        sdiff[pt][t][0] = pts[idx*3+0]-qx;
        sdiff[pt][t][1] = pts[idx*3+1]-qy;
        sdiff[pt][t][2] = pts[idx*3+2]-qz;
        sfeat[pt][t] = feats[idx];
    }
    __syncthreads();
    for (int i = t; i < K_*P_; i += 64) {
        int k = i / P_, p = i % P_;
        float dx = sdiff[pt][k][0] - kp[p*3+0]*extent;
        float dy = sdiff[pt][k][1] - kp[p*3+1]*extent;
        float dz = sdiff[pt][k][2] - kp[p*3+2]*extent;
        float dist = sqrtf(dx*dx+dy*dy+dz*dz);
        sinfl[pt][i] = fmaxf(0.f, 1.f - dist/extent);
    }
    __syncthreads();
    if (t < P_) {
        float acc = 0.f;
        #pragma unroll
        for (int k = 0; k < K_; k++) acc += sinfl[pt][k*P_+t]*sfeat[pt][k];
        sfk[pt][t] = acc;
    }
    __syncthreads();
    float acc = 0.f;
    #pragma unroll
    for (int p = 0; p < P_; p++) acc += sfk[pt][p]*W1[p*64+t];
    out[n*64+t] = acc > 0.f ? acc : 0.1f*acc;
}

// ---------------- gather: fk[n, p*CIN+c] = sum_k infl[n,k,p]*feat[idx,c] ----------
// influence padded to 16 per k -> float4 broadcast LDS; PTS points per block.
template<int CIN, int PTS>
__global__ void gather_fk_kernel(const float* __restrict__ qpts, const float* __restrict__ spts,
                                 const int* __restrict__ neigh, const float* __restrict__ feats,
                                 const float* __restrict__ kp, float extent, float* __restrict__ fk)
{
    __shared__ float sdiff[PTS][K_][3];
    __shared__ int   sidx [PTS][K_];
    __shared__ __align__(16) float sinfl[PTS][K_][16];
    const int tid = threadIdx.x;           // PTS*CIN threads
    const int pt  = tid / CIN;
    const int t   = tid % CIN;
    const int nb  = blockIdx.x * PTS;

    if (tid < PTS * K_) {
        int pp = tid / K_, k = tid % K_;
        int n = nb + pp;
        int idx = neigh[n*K_+k];
        sidx[pp][k] = idx;
        sdiff[pp][k][0] = spts[idx*3+0] - qpts[n*3+0];
        sdiff[pp][k][1] = spts[idx*3+1] - qpts[n*3+1];
        sdiff[pp][k][2] = spts[idx*3+2] - qpts[n*3+2];
    }
    __syncthreads();
    for (int i = tid; i < PTS*K_*16; i += PTS*CIN) {
        int pp = i >> 9;               // /(K_*16)
        int k  = (i >> 4) & (K_-1);
        int p  = i & 15;
        float v = 0.f;
        if (p < P_) {
            float dx = sdiff[pp][k][0] - kp[p*3+0]*extent;
            float dy = sdiff[pp][k][1] - kp[p*3+1]*extent;
            float dz = sdiff[pp][k][2] - kp[p*3+2]*extent;
            v = fmaxf(0.f, 1.f - sqrtf(dx*dx+dy*dy+dz*dz)/extent);
        }
        sinfl[pp][k][p] = v;
    }
    __syncthreads();

    const int n = nb + pt;
    float acc[16];
    #pragma unroll
    for (int p = 0; p < 16; p++) acc[p] = 0.f;
    #pragma unroll 4
    for (int k = 0; k < K_; k++) {
        float f = feats[(size_t)sidx[pt][k]*CIN + t];
        float4 i0 = *(const float4*)&sinfl[pt][k][0];
        float4 i1 = *(const float4*)&sinfl[pt][k][4];
        float4 i2 = *(const float4*)&sinfl[pt][k][8];
        float4 i3 = *(const float4*)&sinfl[pt][k][12];
        acc[0]+=i0.x*f; acc[1]+=i0.y*f; acc[2]+=i0.z*f; acc[3]+=i0.w*f;
        acc[4]+=i1.x*f; acc[5]+=i1.y*f; acc[6]+=i1.z*f; acc[7]+=i1.w*f;
        acc[8]+=i2.x*f; acc[9]+=i2.y*f; acc[10]+=i2.z*f; acc[11]+=i2.w*f;
        acc[12]+=i3.x*f; acc[13]+=i3.y*f; acc[14]+=i3.z*f;
    }
    size_t base = (size_t)n*(P_*CIN) + t;
    #pragma unroll
    for (int p = 0; p < P_; p++) fk[base + (size_t)p*CIN] = acc[p];
}

// ================= tf32 tensor-core GEMM (optionally fused concat A) ==============
// C[M,N] = act(A[M,Kd] @ B[Kd,N]).  Kd%16==0. BM=MF*64, BN=NF*64, BK=16.
// 256 thr = 8 warps (4m x 2n), warp tile (MF*16) x (NF*32).
// CAT: A row r = [ up0[ upidx[r]*c_up .. ] | skip[ r*c_skip .. ] ], Kd = c_up+c_skip,
//      c_up % 16 == 0.

__device__ __forceinline__ uint32_t f2tf32(float x) {
    uint32_t u;
    asm("cvt.rna.tf32.f32 %0, %1;" : "=r"(u) : "f"(x));
    return u;
}
__device__ __forceinline__ void cpasync16(uint32_t dst, const void* src, bool valid) {
    int sz = valid ? 16 : 0;
    asm volatile("cp.async.cg.shared.global [%0], [%1], 16, %2;\n"
                 :: "r"(dst), "l"(src), "r"(sz));
}

template<int MF, int NF, bool LEAKY, bool CAT>
__global__ __launch_bounds__(256)
void gemm_tc(const float* __restrict__ A, const float* __restrict__ B,
             float* __restrict__ C, int M, int N, int Kd,
             const int* __restrict__ upidx, const float* __restrict__ Askip,
             int c_up, int c_skip)
{
    constexpr int BM = MF * 64, BN = NF * 64;
    __shared__ float As[2][BM][20];
    __shared__ float Bs[2][16][BN + 4];

    const int bm = blockIdx.y * BM, bn = blockIdx.x * BN;
    const int tid  = threadIdx.x;
    const int warp = tid >> 5, lane = tid & 31;
    const int wm = warp >> 1, wn = warp & 1;
    const int g  = lane >> 2, tg = lane & 3;

    float c[MF][4*NF][4];
    #pragma unroll
    for (int i = 0; i < MF; i++)
        #pragma unroll
        for (int j = 0; j < 4*NF; j++) {
            c[i][j][0]=0.f; c[i][j][1]=0.f; c[i][j][2]=0.f; c[i][j][3]=0.f;
        }

    const int ar  = tid >> 2;
    const int ac  = (tid & 3) * 4;
    const int bk  = tid >> 4;
    const int bn4 = (tid & 15) * 4;

    int ridx[MF];
    if (CAT) {
        #pragma unroll
        for (int i = 0; i < MF; i++) {
            int r = bm + ar + i * 64;
            ridx[i] = (r < M) ? upidx[r] : 0;
        }
    }

    const int nk = Kd >> 4;

    auto issue = [&](int s, int k0) {
        #pragma unroll
        for (int i = 0; i < MF; i++) {
            int r = ar + i * 64;
            bool v = (bm + r) < M;
            const float* src;
            if (CAT) {
                int kc = k0 + ac;
                src = (kc < c_up) ? (A + (size_t)ridx[i] * c_up + kc)
                                  : (Askip + (size_t)(bm + r) * c_skip + (kc - c_up));
                if (!v) src = A;
            } else {
                src = v ? (A + (size_t)(bm + r) * Kd + k0 + ac) : A;
            }
            cpasync16((uint32_t)__cvta_generic_to_shared(&As[s][r][ac]), src, v);
        }
        #pragma unroll
        for (int j = 0; j < NF; j++) {
            int col = bn4 + j * 64;
            bool v = (bn + col) < N;
            const float* srcb = v ? (B + (size_t)(k0 + bk) * N + bn + col) : B;
            cpasync16((uint32_t)__cvta_generic_to_shared(&Bs[s][bk][col]), srcb, v);
        }
        asm volatile("cp.async.commit_group;\n");
    };

    auto compute = [&](int s) {
        #pragma unroll
        for (int k0 = 0; k0 < 16; k0 += 8) {
            uint32_t a[MF][4], bf[4*NF][2];
            #pragma unroll
            for (int i = 0; i < MF; i++) {
                int r = wm * MF * 16 + i * 16 + g;
                a[i][0] = f2tf32(As[s][r    ][k0 + tg    ]);
                a[i][1] = f2tf32(As[s][r + 8][k0 + tg    ]);
                a[i][2] = f2tf32(As[s][r    ][k0 + tg + 4]);
                a[i][3] = f2tf32(As[s][r + 8][k0 + tg + 4]);
            }
            #pragma unroll
            for (int j = 0; j < 4*NF; j++) {
                int col = wn * NF * 32 + j * 8 + g;
                bf[j][0] = f2tf32(Bs[s][k0 + tg    ][col]);
                bf[j][1] = f2tf32(Bs[s][k0 + tg + 4][col]);
            }
            #pragma unroll
            for (int i = 0; i < MF; i++)
                #pragma unroll
                for (int j = 0; j < 4*NF; j++)
                    asm volatile(
                        "mma.sync.aligned.m16n8k8.row.col.f32.tf32.tf32.f32 "
                        "{%0,%1,%2,%3},{%4,%5,%6,%7},{%8,%9},{%0,%1,%2,%3};\n"
                        : "+f"(c[i][j][0]), "+f"(c[i][j][1]),
                          "+f"(c[i][j][2]), "+f"(c[i][j][3])
                        : "r"(a[i][0]), "r"(a[i][1]), "r"(a[i][2]), "r"(a[i][3]),
                          "r"(bf[j][0]), "r"(bf[j][1]));
        }
    };

    issue(0, 0);
    for (int kt = 0; kt < nk; kt++) {
        if (kt + 1 < nk) {
            issue((kt + 1) & 1, (kt + 1) << 4);
            asm volatile("cp.async.wait_group 1;\n");
        } else {
            asm volatile("cp.async.wait_group 0;\n");
        }
        __syncthreads();
        compute(kt & 1);
        __syncthreads();
    }

    #pragma unroll
    for (int i = 0; i < MF; i++) {
        int r0 = bm + wm * MF * 16 + i * 16 + g;
        #pragma unroll
        for (int j = 0; j < 4*NF; j++) {
            int col = bn + wn * NF * 32 + j * 8 + 2 * tg;
            if (col < N) {
                if (r0 < M) {
                    float v0 = c[i][j][0], v1 = c[i][j][1];
                    if (LEAKY) { v0 = v0 > 0.f ? v0 : 0.1f*v0; v1 = v1 > 0.f ? v1 : 0.1f*v1; }
                    C[(size_t)r0 * N + col]     = v0;
                    C[(size_t)r0 * N + col + 1] = v1;
                }
                if (r0 + 8 < M) {
                    float v2 = c[i][j][2], v3 = c[i][j][3];
                    if (LEAKY) { v2 = v2 > 0.f ? v2 : 0.1f*v2; v3 = v3 > 0.f ? v3 : 0.1f*v3; }
                    C[(size_t)(r0 + 8) * N + col]     = v2;
                    C[(size_t)(r0 + 8) * N + col + 1] = v3;
                }
            }
        }
    }
}

// ---------------- detection head --------------------------------------------------
__global__ void init_gmax_kernel() { g_gmax = 0; }

// one warp per row: rowsum + block-local max -> one atomic per block
__global__ void rowstats_kernel(const float* __restrict__ ff, float* __restrict__ rowsum)
{
    __shared__ float smax[8];
    int row  = (blockIdx.x*blockDim.x + threadIdx.x) >> 5;
    int lane = threadIdx.x & 31;
    int wid  = threadIdx.x >> 5;
    float s = 0.f, m = 0.f;
    if (row < N0_) {
        float v = ff[(size_t)row*32 + lane];
        s = v; m = fmaxf(v, 0.f);
    }
    #pragma unroll
    for (int o = 16; o; o >>= 1) {
        s += __shfl_xor_sync(0xffffffffu, s, o);
        m = fmaxf(m, __shfl_xor_sync(0xffffffffu, m, o));
    }
    if (lane == 0) {
        if (row < N0_) rowsum[row] = s;
        smax[wid] = m;
    }
    __syncthreads();
    if (threadIdx.x == 0) {
        float bm = smax[0];
        #pragma unroll
        for (int w = 1; w < 8; w++) bm = fmaxf(bm, smax[w]);
        atomicMax(&g_gmax, __float_as_int(bm));
    }
}

__global__ void scores_kernel(const int* __restrict__ neigh, const float* __restrict__ ff,
                              const float* __restrict__ rowsum,
                              float* __restrict__ out_fnorm, float* __restrict__ out_scores)
{
    int warp = (blockIdx.x*blockDim.x + threadIdx.x) >> 5;
    int lane = threadIdx.x & 31;
    if (warp >= N0_) return;
    float fraw = ff[(size_t)warp*32 + lane];
    float s2 = fraw*fraw;
    #pragma unroll
    for (int o = 16; o; o >>= 1) s2 += __shfl_xor_sync(0xffffffffu, s2, o);
    float nrm = fmaxf(sqrtf(s2), 1e-12f);
    out_fnorm[(size_t)warp*32 + lane] = fraw / nrm;

    float inv = 1.0f / (__int_as_float(g_gmax) + 1e-6f);
    float f = fraw * inv;
    int myidx = neigh[(size_t)warp*32 + lane];
    float sumf = 0.f, nmax = -1e30f; int nnum = 0;
    #pragma unroll 4
    for (int k = 0; k < K_; k++) {
        int idx = __shfl_sync(0xffffffffu, myidx, k);
        float nf = ff[(size_t)idx*32 + lane] * inv;
        sumf += nf;
        nmax = fmaxf(nmax, nf);
        nnum += (rowsum[idx] != 0.f);
    }
    if (nnum < 1) nnum = 1;
    float mean = sumf / (float)nnum;
    float x = f - mean;
    float lms = fmaxf(x, 0.f) + log1pf(expf(-fabsf(x)));
    float dmax = f;
    #pragma unroll
    for (int o = 16; o; o >>= 1) dmax = fmaxf(dmax, __shfl_xor_sync(0xffffffffu, dmax, o));
    float alls = lms * f / (1e-6f + dmax);
    float sc = alls;
    float det = (f == nmax) ? 1.f : 0.f;
    #pragma unroll
    for (int o = 16; o; o >>= 1) {
        sc  = fmaxf(sc,  __shfl_xor_sync(0xffffffffu, sc, o));
        det = fmaxf(det, __shfl_xor_sync(0xffffffffu, det, o));
    }
    if (lane == 0) out_scores[warp] = sc * det;
}

// ---------------- launch ----------------------------------------------------------
extern "C" void kernel_launch(void* const* d_in, const int* in_sizes, int n_in,
                              void* d_out, int out_size)
{
    const float* features   = (const float*)d_in[0];
    const float* points0    = (const float*)d_in[1];
    const float* points1    = (const float*)d_in[2];
    const float* points2    = (const float*)d_in[3];
    const int*   neighbors0 = (const int*)d_in[4];
    const int*   neighbors1 = (const int*)d_in[5];
    const int*   neighbors2 = (const int*)d_in[6];
    const int*   pools0     = (const int*)d_in[7];
    const int*   pools1     = (const int*)d_in[8];
    const int*   upsamples0 = (const int*)d_in[9];
    const int*   upsamples1 = (const int*)d_in[10];
    const float* kpoints    = (const float*)d_in[11];
    const float* W1  = (const float*)d_in[12];
    const float* W2  = (const float*)d_in[13];
    const float* W3  = (const float*)d_in[14];
    const float* W4  = (const float*)d_in[15];
    const float* W5  = (const float*)d_in[16];
    const float* Wu1 = (const float*)d_in[17];
    const float* Wu2 = (const float*)d_in[18];
    float* out = (float*)d_out;

    float *f1,*f2,*f3,*f4,*f5,*fk,*fu1,*ff,*rowsum;
    cudaGetSymbolAddress((void**)&f1,  g_f1);
    cudaGetSymbolAddress((void**)&f2,  g_f2);
    cudaGetSymbolAddress((void**)&f3,  g_f3);
    cudaGetSymbolAddress((void**)&f4,  g_f4);
    cudaGetSymbolAddress((void**)&f5,  g_f5);
    cudaGetSymbolAddress((void**)&fk,  g_fk);
    cudaGetSymbolAddress((void**)&fu1, g_fu1);
    cudaGetSymbolAddress((void**)&ff,  g_ff);
    cudaGetSymbolAddress((void**)&rowsum, g_rowsum);

    // ---- encoder ----
    conv1_kernel<<<N0_/4, 256>>>(points0, neighbors0, features, kpoints, W1, f1);

    gather_fk_kernel<64,2><<<N1_/2, 128>>>(points1, points0, pools0, f1, kpoints, 0.5f, fk);
    gemm_tc<2,1,true,false><<<dim3(1,(N1_+127)/128), 256>>>(fk, W2, f2, N1_, 64, 960, nullptr, nullptr, 0, 0);

    gather_fk_kernel<64,2><<<N1_/2, 128>>>(points1, points1, neighbors1, f2, kpoints, 1.0f, fk);
    gemm_tc<2,2,true,false><<<dim3(1,(N1_+127)/128), 256>>>(fk, W3, f3, N1_, 128, 960, nullptr, nullptr, 0, 0);

    gather_fk_kernel<128,2><<<N2_/2, 256>>>(points2, points1, pools1, f3, kpoints, 1.0f, fk);
    gemm_tc<1,1,true,false><<<dim3(2,(N2_+63)/64), 256>>>(fk, W4, f4, N2_, 128, 1920, nullptr, nullptr, 0, 0);

    gather_fk_kernel<128,2><<<N2_/2, 256>>>(points2, points2, neighbors2, f4, kpoints, 2.0f, fk);
    gemm_tc<1,2,true,false><<<dim3(2,(N2_+63)/64), 256>>>(fk, W5, f5, N2_, 256, 1920, nullptr, nullptr, 0, 0);

    // ---- decoder (concat fused into GEMM A-load) ----
    gemm_tc<2,2,true,true><<<dim3(1,(N1_+127)/128), 256>>>(f5, Wu1, fu1, N1_, 128, 384,
                                                           upsamples1, f3, 256, 128);
    gemm_tc<2,1,false,true><<<dim3(1,(N0_+127)/128), 256>>>(fu1, Wu2, ff, N0_, 32, 192,
                                                            upsamples0, f1, 128, 64);

    // ---- detection head + outputs ----
    init_gmax_kernel<<<1,1>>>();
    rowstats_kernel<<<(N0_*32 + 255)/256, 256>>>(ff, rowsum);
    scores_kernel<<<(N0_ + 7)/8, 256>>>(neighbors0, ff, rowsum, out, out + (size_t)N0_*32);
}

// round 4
// speedup vs baseline: 2.3975x; 1.3011x over previous
#include <cuda_runtime.h>
#include <cuda_fp16.h>
#include <math.h>
#include <stdint.h>

#define N0_ 60000
#define N1_ 15000
#define N2_ 3750
#define K_  32
#define P_  15

// ---------------- intermediate buffers (device globals; no allocations) ----------
__device__ __align__(16) __half g_f1 [N0_*64];        // skip0
__device__ __align__(16) __half g_f2 [N1_*64];
__device__ __align__(16) __half g_f3 [N1_*128];       // skip1
__device__ __align__(16) __half g_f4 [N2_*128];
__device__ __align__(16) __half g_f5 [N2_*256];
__device__ __align__(16) __half g_fk [N1_*P_*64];     // reused by all gathers
__device__ __align__(16) __half g_fu1[N1_*128];
__device__ __align__(16) float  g_ff [N0_*32];
__device__ __align__(16) __half g_wh [976896];        // all transposed half weights
__device__ float g_rowsum[N0_];
__device__ int g_gmax;

// weight offsets (halfs) inside g_wh
#define WOFF_W2  0
#define WOFF_W3  61440
#define WOFF_W4  184320
#define WOFF_W5  430080
#define WOFF_U1  921600
#define WOFF_U2  970752

// ---------------- weight prep: fp32 [Kd][N] -> half [N][Kd] ----------------------
__global__ void convert_w_kernel(const float* __restrict__ src, __half* __restrict__ dst,
                                 int Kd, int N)
{
    int total = Kd * N;
    for (int i = blockIdx.x*blockDim.x + threadIdx.x; i < total; i += gridDim.x*blockDim.x) {
        int n = i / Kd, k = i - n*Kd;
        dst[i] = __float2half(src[k*N + n]);
    }
}

// ---------------- layer 1: KPConv Cin=1 Cout=64, 4 points / 256-thread block -----
__global__ __launch_bounds__(256)
void conv1_kernel(const float* __restrict__ pts, const int* __restrict__ neigh,
                  const float* __restrict__ feats, const float* __restrict__ kp,
                  const float* __restrict__ W1, __half* __restrict__ out)
{
    const float extent = 0.5f;
    __shared__ float sdiff[4][K_][3];
    __shared__ float sfeat[4][K_];
    __shared__ float sinfl[4][K_*P_];
    __shared__ float sfk[4][P_];
    int pt = threadIdx.x >> 6;
    int t  = threadIdx.x & 63;
    int n  = blockIdx.x * 4 + pt;
    if (t < K_) {
        int idx = neigh[n*K_+t];
        float qx = pts[n*3+0], qy = pts[n*3+1], qz = pts[n*3+2];
        sdiff[pt][t][0] = pts[idx*3+0]-qx;
        sdiff[pt][t][1] = pts[idx*3+1]-qy;
        sdiff[pt][t][2] = pts[idx*3+2]-qz;
        sfeat[pt][t] = feats[idx];
    }
    __syncthreads();
    for (int i = t; i < K_*P_; i += 64) {
        int k = i / P_, p = i % P_;
        float dx = sdiff[pt][k][0] - kp[p*3+0]*extent;
        float dy = sdiff[pt][k][1] - kp[p*3+1]*extent;
        float dz = sdiff[pt][k][2] - kp[p*3+2]*extent;
        float dist = sqrtf(dx*dx+dy*dy+dz*dz);
        sinfl[pt][i] = fmaxf(0.f, 1.f - dist/extent);
    }
    __syncthreads();
    if (t < P_) {
        float acc = 0.f;
        #pragma unroll
        for (int k = 0; k < K_; k++) acc += sinfl[pt][k*P_+t]*sfeat[pt][k];
        sfk[pt][t] = acc;
    }
    __syncthreads();
    float acc = 0.f;
    #pragma unroll
    for (int p = 0; p < P_; p++) acc += sfk[pt][p]*W1[p*64+t];
    out[n*64+t] = __float2half(acc > 0.f ? acc : 0.1f*acc);
}

// ---------------- gather: fk[n, p*CIN+c] = sum_k infl[n,k,p]*feat[idx,c] ----------
// half features/output, 2 channels per thread (half2). TPP = CIN/2 threads/point.
template<int CIN, int PTS>
__global__ void gather_fk_kernel(const float* __restrict__ qpts, const float* __restrict__ spts,
                                 const int* __restrict__ neigh, const __half* __restrict__ feats,
                                 const float* __restrict__ kp, float extent, __half* __restrict__ fk)
{
    constexpr int TPP = CIN / 2;
    __shared__ float sdiff[PTS][K_][3];
    __shared__ int   sidx [PTS][K_];
    __shared__ __align__(16) float sinfl[PTS][K_][16];
    const int tid = threadIdx.x;           // PTS*TPP threads
    const int pt  = tid / TPP;
    const int t   = tid % TPP;
    const int nb  = blockIdx.x * PTS;

    if (tid < PTS * K_) {
        int pp = tid / K_, k = tid % K_;
        int n = nb + pp;
        int idx = neigh[n*K_+k];
        sidx[pp][k] = idx;
        sdiff[pp][k][0] = spts[idx*3+0] - qpts[n*3+0];
        sdiff[pp][k][1] = spts[idx*3+1] - qpts[n*3+1];
        sdiff[pp][k][2] = spts[idx*3+2] - qpts[n*3+2];
    }
    __syncthreads();
    for (int i = tid; i < PTS*K_*16; i += PTS*TPP) {
        int pp = i >> 9;               // /(K_*16)
        int k  = (i >> 4) & (K_-1);
        int p  = i & 15;
        float v = 0.f;
        if (p < P_) {
            float dx = sdiff[pp][k][0] - kp[p*3+0]*extent;
            float dy = sdiff[pp][k][1] - kp[p*3+1]*extent;
            float dz = sdiff[pp][k][2] - kp[p*3+2]*extent;
            v = fmaxf(0.f, 1.f - sqrtf(dx*dx+dy*dy+dz*dz)/extent);
        }
        sinfl[pp][k][p] = v;
    }
    __syncthreads();

    const __half2* feats2 = (const __half2*)feats;
    const int n = nb + pt;
    float ax[15], ay[15];
    #pragma unroll
    for (int p = 0; p < 15; p++) { ax[p] = 0.f; ay[p] = 0.f; }
    #pragma unroll 4
    for (int k = 0; k < K_; k++) {
        float2 fv = __half22float2(feats2[(size_t)sidx[pt][k]*TPP + t]);
        float4 i0 = *(const float4*)&sinfl[pt][k][0];
        float4 i1 = *(const float4*)&sinfl[pt][k][4];
        float4 i2 = *(const float4*)&sinfl[pt][k][8];
        float4 i3 = *(const float4*)&sinfl[pt][k][12];
        ax[0]+=i0.x*fv.x;  ay[0]+=i0.x*fv.y;
        ax[1]+=i0.y*fv.x;  ay[1]+=i0.y*fv.y;
        ax[2]+=i0.z*fv.x;  ay[2]+=i0.z*fv.y;
        ax[3]+=i0.w*fv.x;  ay[3]+=i0.w*fv.y;
        ax[4]+=i1.x*fv.x;  ay[4]+=i1.x*fv.y;
        ax[5]+=i1.y*fv.x;  ay[5]+=i1.y*fv.y;
        ax[6]+=i1.z*fv.x;  ay[6]+=i1.z*fv.y;
        ax[7]+=i1.w*fv.x;  ay[7]+=i1.w*fv.y;
        ax[8]+=i2.x*fv.x;  ay[8]+=i2.x*fv.y;
        ax[9]+=i2.y*fv.x;  ay[9]+=i2.y*fv.y;
        ax[10]+=i2.z*fv.x; ay[10]+=i2.z*fv.y;
        ax[11]+=i2.w*fv.x; ay[11]+=i2.w*fv.y;
        ax[12]+=i3.x*fv.x; ay[12]+=i3.x*fv.y;
        ax[13]+=i3.y*fv.x; ay[13]+=i3.y*fv.y;
        ax[14]+=i3.z*fv.x; ay[14]+=i3.z*fv.y;
    }
    __half2* fk2 = (__half2*)fk;
    size_t base = (size_t)n*(P_*TPP) + t;
    #pragma unroll
    for (int p = 0; p < P_; p++)
        fk2[base + (size_t)p*TPP] = __floats2half2_rn(ax[p], ay[p]);
}

// ================= fp16 tensor-core GEMM (optionally fused concat A) ==============
// C[M,N] = act(A[M,Kd] @ Bt^T), A half row-major, Bt half [N][Kd] (B col-major).
// Kd%32==0. BM=MF*64, BN=NF*64, BK=32 halfs. 256 thr = 8 warps (4m x 2n).
// CAT: A row r = [ up[ upidx[r]*c_up .. ] | skip[ r*c_skip .. ] ], c_up%8==0.

__device__ __forceinline__ void cpasync16(uint32_t dst, const void* src, bool valid) {
    int sz = valid ? 16 : 0;
    asm volatile("cp.async.cg.shared.global [%0], [%1], 16, %2;\n"
                 :: "r"(dst), "l"(src), "r"(sz));
}

template<int MF, int NF, bool LEAKY, bool CAT, bool OUTHALF>
__global__ __launch_bounds__(256)
void gemm_tc(const __half* __restrict__ A, const __half* __restrict__ Bt,
             void* __restrict__ Cv, int M, int N, int Kd,
             const int* __restrict__ upidx, const __half* __restrict__ Askip,
             int c_up, int c_skip)
{
    constexpr int BM = MF * 64, BN = NF * 64;
    __shared__ __align__(16) __half As[2][BM][40];
    __shared__ __align__(16) __half Bs[2][BN][40];

    const int bm = blockIdx.y * BM, bn = blockIdx.x * BN;
    const int tid  = threadIdx.x;
    const int warp = tid >> 5, lane = tid & 31;
    const int wm = warp >> 1, wn = warp & 1;
    const int g  = lane >> 2, tg = lane & 3;

    float c[MF][4*NF][4];
    #pragma unroll
    for (int i = 0; i < MF; i++)
        #pragma unroll
        for (int j = 0; j < 4*NF; j++) {
            c[i][j][0]=0.f; c[i][j][1]=0.f; c[i][j][2]=0.f; c[i][j][3]=0.f;
        }

    const int ar = tid >> 2;           // 0..63 row-in-group
    const int ac = (tid & 3) * 8;      // halfs (16B chunk)

    int ridx[MF];
    if (CAT) {
        #pragma unroll
        for (int i = 0; i < MF; i++) {
            int r = bm + ar + i * 64;
            ridx[i] = (r < M) ? upidx[r] : 0;
        }
    }

    const int nk = Kd >> 5;

    auto issue = [&](int s, int k0) {
        #pragma unroll
        for (int i = 0; i < MF; i++) {
            int r = ar + i * 64;
            bool v = (bm + r) < M;
            const __half* src;
            if (CAT) {
                int kc = k0 + ac;
                src = (kc < c_up) ? (A + (size_t)ridx[i] * c_up + kc)
                                  : (Askip + (size_t)(bm + r) * c_skip + (kc - c_up));
                if (!v) src = A;
            } else {
                src = v ? (A + (size_t)(bm + r) * Kd + k0 + ac) : A;
            }
            cpasync16((uint32_t)__cvta_generic_to_shared(&As[s][r][ac]), src, v);
        }
        #pragma unroll
        for (int j = 0; j < NF; j++) {
            int nrow = ar + j * 64;
            bool v = (bn + nrow) < N;
            const __half* srcb = v ? (Bt + (size_t)(bn + nrow) * Kd + k0 + ac) : Bt;
            cpasync16((uint32_t)__cvta_generic_to_shared(&Bs[s][nrow][ac]), srcb, v);
        }
        asm volatile("cp.async.commit_group;\n");
    };

    auto compute = [&](int s) {
        #pragma unroll
        for (int k0 = 0; k0 < 32; k0 += 16) {
            uint32_t a[MF][4], bf[4*NF][2];
            #pragma unroll
            for (int i = 0; i < MF; i++) {
                int r = wm * MF * 16 + i * 16 + g;
                a[i][0] = *(const uint32_t*)&As[s][r    ][k0 + 2*tg    ];
                a[i][1] = *(const uint32_t*)&As[s][r + 8][k0 + 2*tg    ];
                a[i][2] = *(const uint32_t*)&As[s][r    ][k0 + 2*tg + 8];
                a[i][3] = *(const uint32_t*)&As[s][r + 8][k0 + 2*tg + 8];
            }
            #pragma unroll
            for (int j = 0; j < 4*NF; j++) {
                int col = wn * NF * 32 + j * 8 + g;
                bf[j][0] = *(const uint32_t*)&Bs[s][col][k0 + 2*tg    ];
                bf[j][1] = *(const uint32_t*)&Bs[s][col][k0 + 2*tg + 8];
            }
            #pragma unroll
            for (int i = 0; i < MF; i++)
                #pragma unroll
                for (int j = 0; j < 4*NF; j++)
                    asm volatile(
                        "mma.sync.aligned.m16n8k16.row.col.f32.f16.f16.f32 "
                        "{%0,%1,%2,%3},{%4,%5,%6,%7},{%8,%9},{%0,%1,%2,%3};\n"
                        : "+f"(c[i][j][0]), "+f"(c[i][j][1]),
                          "+f"(c[i][j][2]), "+f"(c[i][j][3])
                        : "r"(a[i][0]), "r"(a[i][1]), "r"(a[i][2]), "r"(a[i][3]),
                          "r"(bf[j][0]), "r"(bf[j][1]));
        }
    };

    issue(0, 0);
    for (int kt = 0; kt < nk; kt++) {
        if (kt + 1 < nk) {
            issue((kt + 1) & 1, (kt + 1) << 5);
            asm volatile("cp.async.wait_group 1;\n");
        } else {
            asm volatile("cp.async.wait_group 0;\n");
        }
        __syncthreads();
        compute(kt & 1);
        __syncthreads();
    }

    __half* Ch = (__half*)Cv;
    float*  Cf = (float*)Cv;
    #pragma unroll
    for (int i = 0; i < MF; i++) {
        int r0 = bm + wm * MF * 16 + i * 16 + g;
        #pragma unroll
        for (int j = 0; j < 4*NF; j++) {
            int col = bn + wn * NF * 32 + j * 8 + 2 * tg;
            if (col < N) {
                if (r0 < M) {
                    float v0 = c[i][j][0], v1 = c[i][j][1];
                    if (LEAKY) { v0 = v0 > 0.f ? v0 : 0.1f*v0; v1 = v1 > 0.f ? v1 : 0.1f*v1; }
                    if (OUTHALF) *(__half2*)&Ch[(size_t)r0 * N + col] = __floats2half2_rn(v0, v1);
                    else { Cf[(size_t)r0 * N + col] = v0; Cf[(size_t)r0 * N + col + 1] = v1; }
                }
                if (r0 + 8 < M) {
                    float v2 = c[i][j][2], v3 = c[i][j][3];
                    if (LEAKY) { v2 = v2 > 0.f ? v2 : 0.1f*v2; v3 = v3 > 0.f ? v3 : 0.1f*v3; }
                    if (OUTHALF) *(__half2*)&Ch[(size_t)(r0+8) * N + col] = __floats2half2_rn(v2, v3);
                    else { Cf[(size_t)(r0+8) * N + col] = v2; Cf[(size_t)(r0+8) * N + col + 1] = v3; }
                }
            }
        }
    }
}

// ---------------- detection head --------------------------------------------------
__global__ void init_gmax_kernel() { g_gmax = 0; }

__global__ void rowstats_kernel(const float* __restrict__ ff, float* __restrict__ rowsum)
{
    __shared__ float smax[8];
    int row  = (blockIdx.x*blockDim.x + threadIdx.x) >> 5;
    int lane = threadIdx.x & 31;
    int wid  = threadIdx.x >> 5;
    float s = 0.f, m = 0.f;
    if (row < N0_) {
        float v = ff[(size_t)row*32 + lane];
        s = v; m = fmaxf(v, 0.f);
    }
    #pragma unroll
    for (int o = 16; o; o >>= 1) {
        s += __shfl_xor_sync(0xffffffffu, s, o);
        m = fmaxf(m, __shfl_xor_sync(0xffffffffu, m, o));
    }
    if (lane == 0) {
        if (row < N0_) rowsum[row] = s;
        smax[wid] = m;
    }
    __syncthreads();
    if (threadIdx.x == 0) {
        float bm = smax[0];
        #pragma unroll
        for (int w = 1; w < 8; w++) bm = fmaxf(bm, smax[w]);
        atomicMax(&g_gmax, __float_as_int(bm));
    }
}

__global__ void scores_kernel(const int* __restrict__ neigh, const float* __restrict__ ff,
                              const float* __restrict__ rowsum,
                              float* __restrict__ out_fnorm, float* __restrict__ out_scores)
{
    int warp = (blockIdx.x*blockDim.x + threadIdx.x) >> 5;
    int lane = threadIdx.x & 31;
    if (warp >= N0_) return;
    float fraw = ff[(size_t)warp*32 + lane];
    float s2 = fraw*fraw;
    #pragma unroll
    for (int o = 16; o; o >>= 1) s2 += __shfl_xor_sync(0xffffffffu, s2, o);
    float nrm = fmaxf(sqrtf(s2), 1e-12f);
    out_fnorm[(size_t)warp*32 + lane] = fraw / nrm;

    float inv = 1.0f / (__int_as_float(g_gmax) + 1e-6f);
    float f = fraw * inv;
    int myidx = neigh[(size_t)warp*32 + lane];
    float sumf = 0.f, nmax = -1e30f; int nnum = 0;
    #pragma unroll 4
    for (int k = 0; k < K_; k++) {
        int idx = __shfl_sync(0xffffffffu, myidx, k);
        float nf = ff[(size_t)idx*32 + lane] * inv;
        sumf += nf;
        nmax = fmaxf(nmax, nf);
        nnum += (rowsum[idx] != 0.f);
    }
    if (nnum < 1) nnum = 1;
    float mean = sumf / (float)nnum;
    float x = f - mean;
    float lms = fmaxf(x, 0.f) + log1pf(expf(-fabsf(x)));
    float dmax = f;
    #pragma unroll
    for (int o = 16; o; o >>= 1) dmax = fmaxf(dmax, __shfl_xor_sync(0xffffffffu, dmax, o));
    float sc = lms * f / (1e-6f + dmax);
    float det = (f == nmax) ? 1.f : 0.f;
    #pragma unroll
    for (int o = 16; o; o >>= 1) {
        sc  = fmaxf(sc,  __shfl_xor_sync(0xffffffffu, sc, o));
        det = fmaxf(det, __shfl_xor_sync(0xffffffffu, det, o));
    }
    if (lane == 0) out_scores[warp] = sc * det;
}

// ---------------- launch ----------------------------------------------------------
extern "C" void kernel_launch(void* const* d_in, const int* in_sizes, int n_in,
                              void* d_out, int out_size)
{
    const float* features   = (const float*)d_in[0];
    const float* points0    = (const float*)d_in[1];
    const float* points1    = (const float*)d_in[2];
    const float* points2    = (const float*)d_in[3];
    const int*   neighbors0 = (const int*)d_in[4];
    const int*   neighbors1 = (const int*)d_in[5];
    const int*   neighbors2 = (const int*)d_in[6];
    const int*   pools0     = (const int*)d_in[7];
    const int*   pools1     = (const int*)d_in[8];
    const int*   upsamples0 = (const int*)d_in[9];
    const int*   upsamples1 = (const int*)d_in[10];
    const float* kpoints    = (const float*)d_in[11];
    const float* W1  = (const float*)d_in[12];
    const float* W2  = (const float*)d_in[13];
    const float* W3  = (const float*)d_in[14];
    const float* W4  = (const float*)d_in[15];
    const float* W5  = (const float*)d_in[16];
    const float* Wu1 = (const float*)d_in[17];
    const float* Wu2 = (const float*)d_in[18];
    float* out = (float*)d_out;

    __half *f1,*f2,*f3,*f4,*f5,*fk,*fu1,*wh;
    float *ff,*rowsum;
    cudaGetSymbolAddress((void**)&f1,  g_f1);
    cudaGetSymbolAddress((void**)&f2,  g_f2);
    cudaGetSymbolAddress((void**)&f3,  g_f3);
    cudaGetSymbolAddress((void**)&f4,  g_f4);
    cudaGetSymbolAddress((void**)&f5,  g_f5);
    cudaGetSymbolAddress((void**)&fk,  g_fk);
    cudaGetSymbolAddress((void**)&fu1, g_fu1);
    cudaGetSymbolAddress((void**)&wh,  g_wh);
    cudaGetSymbolAddress((void**)&ff,  g_ff);
    cudaGetSymbolAddress((void**)&rowsum, g_rowsum);

    // ---- weight prep (graph-capturable, deterministic) ----
    convert_w_kernel<<<64, 256>>>(W2,  wh + WOFF_W2, 960, 64);
    convert_w_kernel<<<64, 256>>>(W3,  wh + WOFF_W3, 960, 128);
    convert_w_kernel<<<64, 256>>>(W4,  wh + WOFF_W4, 1920, 128);
    convert_w_kernel<<<128,256>>>(W5,  wh + WOFF_W5, 1920, 256);
    convert_w_kernel<<<32, 256>>>(Wu1, wh + WOFF_U1, 384, 128);
    convert_w_kernel<<<8,  256>>>(Wu2, wh + WOFF_U2, 192, 32);

    // ---- encoder ----
    conv1_kernel<<<N0_/4, 256>>>(points0, neighbors0, features, kpoints, W1, f1);

    gather_fk_kernel<64,4><<<N1_/4, 128>>>(points1, points0, pools0, f1, kpoints, 0.5f, fk);
    gemm_tc<2,1,true,false,true><<<dim3(1,(N1_+127)/128), 256>>>(fk, wh+WOFF_W2, f2, N1_, 64, 960, nullptr, nullptr, 0, 0);

    gather_fk_kernel<64,4><<<N1_/4, 128>>>(points1, points1, neighbors1, f2, kpoints, 1.0f, fk);
    gemm_tc<2,2,true,false,true><<<dim3(1,(N1_+127)/128), 256>>>(fk, wh+WOFF_W3, f3, N1_, 128, 960, nullptr, nullptr, 0, 0);

    gather_fk_kernel<128,2><<<N2_/2, 128>>>(points2, points1, pools1, f3, kpoints, 1.0f, fk);
    gemm_tc<1,1,true,false,true><<<dim3(2,(N2_+63)/64), 256>>>(fk, wh+WOFF_W4, f4, N2_, 128, 1920, nullptr, nullptr, 0, 0);

    gather_fk_kernel<128,2><<<N2_/2, 128>>>(points2, points2, neighbors2, f4, kpoints, 2.0f, fk);
    gemm_tc<1,2,true,false,true><<<dim3(2,(N2_+63)/64), 256>>>(fk, wh+WOFF_W5, f5, N2_, 256, 1920, nullptr, nullptr, 0, 0);

    // ---- decoder (concat fused into GEMM A-load) ----
    gemm_tc<2,2,true,true,true><<<dim3(1,(N1_+127)/128), 256>>>(f5, wh+WOFF_U1, fu1, N1_, 128, 384,
                                                                upsamples1, f3, 256, 128);
    gemm_tc<2,1,false,true,false><<<dim3(1,(N0_+127)/128), 256>>>(fu1, wh+WOFF_U2, ff, N0_, 32, 192,
                                                                  upsamples0, f1, 128, 64);

    // ---- detection head + outputs ----
    init_gmax_kernel<<<1,1>>>();
    rowstats_kernel<<<(N0_*32 + 255)/256, 256>>>(ff, rowsum);
    scores_kernel<<<(N0_ + 7)/8, 256>>>(neighbors0, ff, rowsum, out, out + (size_t)N0_*32);
}

// round 6
// speedup vs baseline: 2.9251x; 1.2201x over previous
#include <cuda_runtime.h>
#include <cuda_fp16.h>
#include <math.h>
#include <stdint.h>

#define N0_ 60000
#define N1_ 15000
#define N2_ 3750
#define K_  32
#define P_  15

// ---------------- intermediate buffers (device globals; no allocations) ----------
__device__ __align__(16) __half g_f1 [N0_*64];        // skip0
__device__ __align__(16) __half g_f2 [N1_*64];
__device__ __align__(16) __half g_f3 [N1_*128];       // skip1
__device__ __align__(16) __half g_f4 [N2_*128];
__device__ __align__(16) __half g_f5 [N2_*256];
__device__ __align__(16) __half g_fk [N1_*P_*64];     // reused by all gathers
__device__ __align__(16) __half g_fu1[N1_*128];
__device__ __align__(16) float  g_ff [N0_*32];
__device__ __align__(16) __half g_wh [976896];        // all transposed half weights
__device__ float g_rowsum[N0_];
__device__ int g_gmax;

#define WOFF_W2  0
#define WOFF_W3  61440
#define WOFF_W4  184320
#define WOFF_W5  430080
#define WOFF_U1  921600
#define WOFF_U2  970752

// ---------------- weight prep: fp32 [Kd][N] -> half [N][Kd], coalesced transpose --
__global__ __launch_bounds__(256)
void convert_w_kernel(const float* __restrict__ src, __half* __restrict__ dst,
                      int Kd, int N)
{
    __shared__ float tile[32][33];
    int kb = blockIdx.x*32, nb = blockIdx.y*32;
    int tx = threadIdx.x & 31, ty = threadIdx.x >> 5;   // 32 x 8
    #pragma unroll
    for (int r = 0; r < 32; r += 8) {
        int k = kb + ty + r, nn = nb + tx;
        tile[ty+r][tx] = (k < Kd && nn < N) ? src[(size_t)k*N + nn] : 0.f;
    }
    __syncthreads();
    #pragma unroll
    for (int r = 0; r < 32; r += 8) {
        int nn = nb + ty + r, k = kb + tx;
        if (nn < N && k < Kd) dst[(size_t)nn*Kd + k] = __float2half(tile[tx][ty+r]);
    }
}

// ---------------- layer 1: KPConv Cin=1 Cout=64 ----------------------------------
__global__ __launch_bounds__(256)
void conv1_kernel(const float* __restrict__ pts, const int* __restrict__ neigh,
                  const float* __restrict__ feats, const float* __restrict__ kp,
                  const float* __restrict__ W1, __half* __restrict__ out)
{
    const float extent = 0.5f;
    __shared__ float sdiff[4][K_][3];
    __shared__ float sfeat[4][K_];
    __shared__ float sinfl[4][K_*P_];
    __shared__ float sfk[4][P_];
    int pt = threadIdx.x >> 6;
    int t  = threadIdx.x & 63;
    int n  = blockIdx.x * 4 + pt;
    if (t < K_) {
        int idx = neigh[n*K_+t];
        float qx = pts[n*3+0], qy = pts[n*3+1], qz = pts[n*3+2];
        sdiff[pt][t][0] = pts[idx*3+0]-qx;
        sdiff[pt][t][1] = pts[idx*3+1]-qy;
        sdiff[pt][t][2] = pts[idx*3+2]-qz;
        sfeat[pt][t] = feats[idx];
    }
    __syncthreads();
    for (int i = t; i < K_*P_; i += 64) {
        int k = i / P_, p = i % P_;
        float dx = sdiff[pt][k][0] - kp[p*3+0]*extent;
        float dy = sdiff[pt][k][1] - kp[p*3+1]*extent;
        float dz = sdiff[pt][k][2] - kp[p*3+2]*extent;
        float dist = sqrtf(dx*dx+dy*dy+dz*dz);
        sinfl[pt][i] = fmaxf(0.f, 1.f - dist/extent);
    }
    __syncthreads();
    if (t < P_) {
        float acc = 0.f;
        #pragma unroll
        for (int k = 0; k < K_; k++) acc += sinfl[pt][k*P_+t]*sfeat[pt][k];
        sfk[pt][t] = acc;
    }
    __syncthreads();
    float acc = 0.f;
    #pragma unroll
    for (int p = 0; p < P_; p++) acc += sfk[pt][p]*W1[p*64+t];
    out[n*64+t] = __float2half(acc > 0.f ? acc : 0.1f*acc);
}

// ---------------- tensor-core gather ----------------------------------------------
// fk[n, p*CIN+c] = sum_k infl[n,k,p] * feat[idx[n,k], c], computed as per-point
// MMA: A = nf^T (channels x neighbors, via ldmatrix.trans), B = infl (neighbors x P),
// D = fk^T (channels x P). One warp per point.
__device__ __forceinline__ void ldsm4t(uint32_t& r0, uint32_t& r1, uint32_t& r2,
                                       uint32_t& r3, uint32_t addr)
{
    asm volatile("ldmatrix.sync.aligned.m8n8.x4.trans.shared.b16 {%0,%1,%2,%3}, [%4];"
                 : "=r"(r0), "=r"(r1), "=r"(r2), "=r"(r3) : "r"(addr));
}

template<int CIN, int WPB>
__global__ __launch_bounds__(32*WPB)
void gather_mma_kernel(const float* __restrict__ qpts, const float* __restrict__ spts,
                       const int* __restrict__ neigh, const __half* __restrict__ feats,
                       const float* __restrict__ kp, float extent,
                       __half* __restrict__ fk, int Npts)
{
    constexpr int STR = CIN + 8;        // halfs per nf row (pad: conflict-free ldsm)
    constexpr int MT  = CIN / 16;
    __shared__ __half nf[WPB][32][STR];
    __shared__ float  sdiff[WPB][32][4];
    __shared__ int    sidx[WPB][32];

    const int w    = threadIdx.x >> 5;
    const int lane = threadIdx.x & 31;
    const int n    = blockIdx.x * WPB + w;
    if (n >= Npts) return;
    const int g = lane >> 2, t4 = lane & 3;

    // neighbor index + diff
    {
        int idx = neigh[n*K_ + lane];
        sidx[w][lane] = idx;
        float qx = qpts[n*3+0], qy = qpts[n*3+1], qz = qpts[n*3+2];
        sdiff[w][lane][0] = spts[idx*3+0]-qx;
        sdiff[w][lane][1] = spts[idx*3+1]-qy;
        sdiff[w][lane][2] = spts[idx*3+2]-qz;
    }
    __syncwarp();

    // stage gathered features (coalesced 16B chunks)
    if (CIN == 64) {
        #pragma unroll
        for (int r = 0; r < 8; r++) {
            int row = r*4 + (lane>>3);
            int ch  = (lane&7)*8;
            uint4 v = *(const uint4*)(feats + (size_t)sidx[w][row]*CIN + ch);
            *(uint4*)&nf[w][row][ch] = v;
        }
    } else {
        #pragma unroll
        for (int r = 0; r < 16; r++) {
            int row = r*2 + (lane>>4);
            int ch  = (lane&15)*8;
            uint4 v = *(const uint4*)(feats + (size_t)sidx[w][row]*CIN + ch);
            *(uint4*)&nf[w][row][ch] = v;
        }
    }

    // influence -> B fragments (m16n8k16.row.col layout), computed in registers
    const float inv_e = 1.0f / extent;
    uint32_t bfr[2][2][2];
    #pragma unroll
    for (int nt = 0; nt < 2; nt++) {
        int p = nt*8 + g;
        bool pv = p < P_;
        float px = 0.f, py = 0.f, pz = 0.f;
        if (pv) {
            px = kp[p*3+0]*extent; py = kp[p*3+1]*extent; pz = kp[p*3+2]*extent;
        }
        #pragma unroll
        for (int ks = 0; ks < 2; ks++) {
            int kb = ks*16 + 2*t4;
            float v[4];
            #pragma unroll
            for (int j = 0; j < 4; j++) {
                int k = kb + (j>>1)*8 + (j&1);
                float dx = sdiff[w][k][0]-px;
                float dy = sdiff[w][k][1]-py;
                float dz = sdiff[w][k][2]-pz;
                float d = sqrtf(dx*dx+dy*dy+dz*dz);
                v[j] = pv ? fmaxf(0.f, 1.f - d*inv_e) : 0.f;
            }
            __half2 h0 = __floats2half2_rn(v[0], v[1]);
            __half2 h1 = __floats2half2_rn(v[2], v[3]);
            bfr[nt][ks][0] = *reinterpret_cast<uint32_t*>(&h0);
            bfr[nt][ks][1] = *reinterpret_cast<uint32_t*>(&h1);
        }
    }
    __syncwarp();

    // MMAs: D[c][p] += nf^T @ infl
    float d[MT][2][4];
    #pragma unroll
    for (int mt = 0; mt < MT; mt++)
        #pragma unroll
        for (int nt = 0; nt < 2; nt++) {
            d[mt][nt][0]=0.f; d[mt][nt][1]=0.f; d[mt][nt][2]=0.f; d[mt][nt][3]=0.f;
        }
    uint32_t nf_base = (uint32_t)__cvta_generic_to_shared(&nf[w][0][0]);
    const int grp = lane >> 3, jj = lane & 7;
    #pragma unroll
    for (int mt = 0; mt < MT; mt++) {
        #pragma unroll
        for (int ks = 0; ks < 2; ks++) {
            int krow = ks*16 + ((grp & 2) ? 8 : 0) + jj;
            int mcol = mt*16 + ((grp & 1) ? 8 : 0);
            uint32_t addr = nf_base + (uint32_t)(krow*STR + mcol)*2u;
            uint32_t a0,a1,a2,a3;
            ldsm4t(a0,a1,a2,a3, addr);
            #pragma unroll
            for (int nt = 0; nt < 2; nt++)
                asm volatile(
                    "mma.sync.aligned.m16n8k16.row.col.f32.f16.f16.f32 "
                    "{%0,%1,%2,%3},{%4,%5,%6,%7},{%8,%9},{%0,%1,%2,%3};\n"
                    : "+f"(d[mt][nt][0]), "+f"(d[mt][nt][1]),
                      "+f"(d[mt][nt][2]), "+f"(d[mt][nt][3])
                    : "r"(a0), "r"(a1), "r"(a2), "r"(a3),
                      "r"(bfr[nt][ks][0]), "r"(bfr[nt][ks][1]));
        }
    }
    __syncwarp();

    // D -> smem (reuse nf as sfk[p][c], rows 0..15), then coalesced global store
    #pragma unroll
    for (int mt = 0; mt < MT; mt++) {
        int c = mt*16 + g;
        #pragma unroll
        for (int nt = 0; nt < 2; nt++) {
            int p0 = nt*8 + 2*t4;
            nf[w][p0  ][c  ] = __float2half(d[mt][nt][0]);
            nf[w][p0+1][c  ] = __float2half(d[mt][nt][1]);
            nf[w][p0  ][c+8] = __float2half(d[mt][nt][2]);
            nf[w][p0+1][c+8] = __float2half(d[mt][nt][3]);
        }
    }
    __syncwarp();
    constexpr int CH = P_ * CIN / 8;   // 16B chunks per point (120 / 240)
    #pragma unroll
    for (int cid = lane; cid < CH; cid += 32) {
        int p = cid / (CIN/8), cc = cid % (CIN/8);
        uint4 v = *(const uint4*)&nf[w][p][cc*8];
        *(uint4*)(fk + (size_t)n*(P_*CIN) + cid*8) = v;
    }
}

// ================= fp16 tensor-core GEMM (fused concat / row-stats) ==============
__device__ __forceinline__ void cpasync16(uint32_t dst, const void* src, bool valid) {
    int sz = valid ? 16 : 0;
    asm volatile("cp.async.cg.shared.global [%0], [%1], 16, %2;\n"
                 :: "r"(dst), "l"(src), "r"(sz));
}

template<int MF, int NF, bool LEAKY, bool CAT, bool OUTHALF, bool STATS>
__global__ __launch_bounds__(256)
void gemm_tc(const __half* __restrict__ A, const __half* __restrict__ Bt,
             void* __restrict__ Cv, int M, int N, int Kd,
             const int* __restrict__ upidx, const __half* __restrict__ Askip,
             int c_up, int c_skip, float* __restrict__ rowsum, int* __restrict__ gmaxp)
{
    constexpr int BM = MF * 64, BN = NF * 64;
    __shared__ __align__(16) __half As[2][BM][40];
    __shared__ __align__(16) __half Bs[2][BN][40];
    __shared__ float swm[8];

    const int bm = blockIdx.y * BM, bn = blockIdx.x * BN;
    const int tid  = threadIdx.x;
    const int warp = tid >> 5, lane = tid & 31;
    const int wm = warp >> 1, wn = warp & 1;
    const int g  = lane >> 2, tg = lane & 3;

    float c[MF][4*NF][4];
    #pragma unroll
    for (int i = 0; i < MF; i++)
        #pragma unroll
        for (int j = 0; j < 4*NF; j++) {
            c[i][j][0]=0.f; c[i][j][1]=0.f; c[i][j][2]=0.f; c[i][j][3]=0.f;
        }

    const int ar = tid >> 2;
    const int ac = (tid & 3) * 8;

    int ridx[MF];
    if (CAT) {
        #pragma unroll
        for (int i = 0; i < MF; i++) {
            int r = bm + ar + i * 64;
            ridx[i] = (r < M) ? upidx[r] : 0;
        }
    }

    const int nk = Kd >> 5;

    auto issue = [&](int s, int k0) {
        #pragma unroll
        for (int i = 0; i < MF; i++) {
            int r = ar + i * 64;
            bool v = (bm + r) < M;
            const __half* src;
            if (CAT) {
                int kc = k0 + ac;
                src = (kc < c_up) ? (A + (size_t)ridx[i] * c_up + kc)
                                  : (Askip + (size_t)(bm + r) * c_skip + (kc - c_up));
                if (!v) src = A;
            } else {
                src = v ? (A + (size_t)(bm + r) * Kd + k0 + ac) : A;
            }
            cpasync16((uint32_t)__cvta_generic_to_shared(&As[s][r][ac]), src, v);
        }
        #pragma unroll
        for (int j = 0; j < NF; j++) {
            int nrow = ar + j * 64;
            bool v = (bn + nrow) < N;
            const __half* srcb = v ? (Bt + (size_t)(bn + nrow) * Kd + k0 + ac) : Bt;
            cpasync16((uint32_t)__cvta_generic_to_shared(&Bs[s][nrow][ac]), srcb, v);
        }
        asm volatile("cp.async.commit_group;\n");
    };

    auto compute = [&](int s) {
        #pragma unroll
        for (int k0 = 0; k0 < 32; k0 += 16) {
            uint32_t a[MF][4], bf[4*NF][2];
            #pragma unroll
            for (int i = 0; i < MF; i++) {
                int r = wm * MF * 16 + i * 16 + g;
                a[i][0] = *(const uint32_t*)&As[s][r    ][k0 + 2*tg    ];
                a[i][1] = *(const uint32_t*)&As[s][r + 8][k0 + 2*tg    ];
                a[i][2] = *(const uint32_t*)&As[s][r    ][k0 + 2*tg + 8];
                a[i][3] = *(const uint32_t*)&As[s][r + 8][k0 + 2*tg + 8];
            }
            #pragma unroll
            for (int j = 0; j < 4*NF; j++) {
                int col = wn * NF * 32 + j * 8 + g;
                bf[j][0] = *(const uint32_t*)&Bs[s][col][k0 + 2*tg    ];
                bf[j][1] = *(const uint32_t*)&Bs[s][col][k0 + 2*tg + 8];
            }
            #pragma unroll
            for (int i = 0; i < MF; i++)
                #pragma unroll
                for (int j = 0; j < 4*NF; j++)
                    asm volatile(
                        "mma.sync.aligned.m16n8k16.row.col.f32.f16.f16.f32 "
                        "{%0,%1,%2,%3},{%4,%5,%6,%7},{%8,%9},{%0,%1,%2,%3};\n"
                        : "+f"(c[i][j][0]), "+f"(c[i][j][1]),
                          "+f"(c[i][j][2]), "+f"(c[i][j][3])
                        : "r"(a[i][0]), "r"(a[i][1]), "r"(a[i][2]), "r"(a[i][3]),
                          "r"(bf[j][0]), "r"(bf[j][1]));
        }
    };

    issue(0, 0);
    for (int kt = 0; kt < nk; kt++) {
        if (kt + 1 < nk) {
            issue((kt + 1) & 1, (kt + 1) << 5);
            asm volatile("cp.async.wait_group 1;\n");
        } else {
            asm volatile("cp.async.wait_group 0;\n");
        }
        __syncthreads();
        compute(kt & 1);
        __syncthreads();
    }

    __half* Ch = (__half*)Cv;
    float*  Cf = (float*)Cv;
    #pragma unroll
    for (int i = 0; i < MF; i++) {
        int r0 = bm + wm * MF * 16 + i * 16 + g;
        #pragma unroll
        for (int j = 0; j < 4*NF; j++) {
            int col = bn + wn * NF * 32 + j * 8 + 2 * tg;
            if (col < N) {
                if (r0 < M) {
                    float v0 = c[i][j][0], v1 = c[i][j][1];
                    if (LEAKY) { v0 = v0 > 0.f ? v0 : 0.1f*v0; v1 = v1 > 0.f ? v1 : 0.1f*v1; }
                    if (OUTHALF) *(__half2*)&Ch[(size_t)r0 * N + col] = __floats2half2_rn(v0, v1);
                    else { Cf[(size_t)r0 * N + col] = v0; Cf[(size_t)r0 * N + col + 1] = v1; }
                }
                if (r0 + 8 < M) {
                    float v2 = c[i][j][2], v3 = c[i][j][3];
                    if (LEAKY) { v2 = v2 > 0.f ? v2 : 0.1f*v2; v3 = v3 > 0.f ? v3 : 0.1f*v3; }
                    if (OUTHALF) *(__half2*)&Ch[(size_t)(r0+8) * N + col] = __floats2half2_rn(v2, v3);
                    else { Cf[(size_t)(r0+8) * N + col] = v2; Cf[(size_t)(r0+8) * N + col + 1] = v3; }
                }
            }
        }
    }

    if (STATS) {
        // N <= 32: all valid columns live in wn==0 warps (cols 0..31, zero-filled >=N).
        float wmax = 0.f;
        if (wn == 0) {
            #pragma unroll
            for (int i = 0; i < MF; i++) {
                float sl = 0.f, sh = 0.f, ml = 0.f, mh = 0.f;
                #pragma unroll
                for (int j = 0; j < 4*NF; j++) {
                    sl += c[i][j][0] + c[i][j][1];
                    sh += c[i][j][2] + c[i][j][3];
                    ml = fmaxf(ml, fmaxf(c[i][j][0], c[i][j][1]));
                    mh = fmaxf(mh, fmaxf(c[i][j][2], c[i][j][3]));
                }
                sl += __shfl_xor_sync(0xffffffffu, sl, 1);
                sl += __shfl_xor_sync(0xffffffffu, sl, 2);
                sh += __shfl_xor_sync(0xffffffffu, sh, 1);
                sh += __shfl_xor_sync(0xffffffffu, sh, 2);
                ml = fmaxf(ml, __shfl_xor_sync(0xffffffffu, ml, 1));
                ml = fmaxf(ml, __shfl_xor_sync(0xffffffffu, ml, 2));
                mh = fmaxf(mh, __shfl_xor_sync(0xffffffffu, mh, 1));
                mh = fmaxf(mh, __shfl_xor_sync(0xffffffffu, mh, 2));
                int r0 = bm + wm * MF * 16 + i * 16 + g;
                if (tg == 0) {
                    if (r0 < M)     rowsum[r0]     = sl;
                    if (r0 + 8 < M) rowsum[r0 + 8] = sh;
                }
                wmax = fmaxf(wmax, fmaxf(ml, mh));
            }
        }
        #pragma unroll
        for (int o = 16; o; o >>= 1)
            wmax = fmaxf(wmax, __shfl_xor_sync(0xffffffffu, wmax, o));
        if (lane == 0) swm[warp] = wmax;
        __syncthreads();
        if (tid == 0) {
            float bmv = swm[0];
            #pragma unroll
            for (int ww = 1; ww < 8; ww++) bmv = fmaxf(bmv, swm[ww]);
            atomicMax(gmaxp, __float_as_int(fmaxf(bmv, 0.f)));
        }
    }
}

// ---------------- detection head --------------------------------------------------
__global__ void init_gmax_kernel() { g_gmax = 0; }

__global__ void scores_kernel(const int* __restrict__ neigh, const float* __restrict__ ff,
                              const float* __restrict__ rowsum,
                              float* __restrict__ out_fnorm, float* __restrict__ out_scores)
{
    int warp = (blockIdx.x*blockDim.x + threadIdx.x) >> 5;
    int lane = threadIdx.x & 31;
    if (warp >= N0_) return;
    float fraw = ff[(size_t)warp*32 + lane];
    float s2 = fraw*fraw;
    #pragma unroll
    for (int o = 16; o; o >>= 1) s2 += __shfl_xor_sync(0xffffffffu, s2, o);
    float nrm = fmaxf(sqrtf(s2), 1e-12f);
    out_fnorm[(size_t)warp*32 + lane] = fraw / nrm;

    float inv = 1.0f / (__int_as_float(g_gmax) + 1e-6f);
    float f = fraw * inv;
    int myidx = neigh[(size_t)warp*32 + lane];
    float sumf = 0.f, nmax = -1e30f; int nnum = 0;
    #pragma unroll 4
    for (int k = 0; k < K_; k++) {
        int idx = __shfl_sync(0xffffffffu, myidx, k);
        float nf = ff[(size_t)idx*32 + lane] * inv;
        sumf += nf;
        nmax = fmaxf(nmax, nf);
        nnum += (rowsum[idx] != 0.f);
    }
    if (nnum < 1) nnum = 1;
    float mean = sumf / (float)nnum;
    float x = f - mean;
    float lms = fmaxf(x, 0.f) + log1pf(expf(-fabsf(x)));
    float dmax = f;
    #pragma unroll
    for (int o = 16; o; o >>= 1) dmax = fmaxf(dmax, __shfl_xor_sync(0xffffffffu, dmax, o));
    float sc = lms * f / (1e-6f + dmax);
    float det = (f == nmax) ? 1.f : 0.f;
    #pragma unroll
    for (int o = 16; o; o >>= 1) {
        sc  = fmaxf(sc,  __shfl_xor_sync(0xffffffffu, sc, o));
        det = fmaxf(det, __shfl_xor_sync(0xffffffffu, det, o));
    }
    if (lane == 0) out_scores[warp] = sc * det;
}

// ---------------- launch ----------------------------------------------------------
extern "C" void kernel_launch(void* const* d_in, const int* in_sizes, int n_in,
                              void* d_out, int out_size)
{
    const float* features   = (const float*)d_in[0];
    const float* points0    = (const float*)d_in[1];
    const float* points1    = (const float*)d_in[2];
    const float* points2    = (const float*)d_in[3];
    const int*   neighbors0 = (const int*)d_in[4];
    const int*   neighbors1 = (const int*)d_in[5];
    const int*   neighbors2 = (const int*)d_in[6];
    const int*   pools0     = (const int*)d_in[7];
    const int*   pools1     = (const int*)d_in[8];
    const int*   upsamples0 = (const int*)d_in[9];
    const int*   upsamples1 = (const int*)d_in[10];
    const float* kpoints    = (const float*)d_in[11];
    const float* W1  = (const float*)d_in[12];
    const float* W2  = (const float*)d_in[13];
    const float* W3  = (const float*)d_in[14];
    const float* W4  = (const float*)d_in[15];
    const float* W5  = (const float*)d_in[16];
    const float* Wu1 = (const float*)d_in[17];
    const float* Wu2 = (const float*)d_in[18];
    float* out = (float*)d_out;

    __half *f1,*f2,*f3,*f4,*f5,*fk,*fu1,*wh;
    float *ff,*rowsum;
    int *gmaxp;
    cudaGetSymbolAddress((void**)&f1,  g_f1);
    cudaGetSymbolAddress((void**)&f2,  g_f2);
    cudaGetSymbolAddress((void**)&f3,  g_f3);
    cudaGetSymbolAddress((void**)&f4,  g_f4);
    cudaGetSymbolAddress((void**)&f5,  g_f5);
    cudaGetSymbolAddress((void**)&fk,  g_fk);
    cudaGetSymbolAddress((void**)&fu1, g_fu1);
    cudaGetSymbolAddress((void**)&wh,  g_wh);
    cudaGetSymbolAddress((void**)&ff,  g_ff);
    cudaGetSymbolAddress((void**)&rowsum, g_rowsum);
    cudaGetSymbolAddress((void**)&gmaxp,  g_gmax);

    // ---- weight prep ----
    convert_w_kernel<<<dim3(30,2), 256>>>(W2,  wh + WOFF_W2, 960, 64);
    convert_w_kernel<<<dim3(30,4), 256>>>(W3,  wh + WOFF_W3, 960, 128);
    convert_w_kernel<<<dim3(60,4), 256>>>(W4,  wh + WOFF_W4, 1920, 128);
    convert_w_kernel<<<dim3(60,8), 256>>>(W5,  wh + WOFF_W5, 1920, 256);
    convert_w_kernel<<<dim3(12,4), 256>>>(Wu1, wh + WOFF_U1, 384, 128);
    convert_w_kernel<<<dim3(6,1),  256>>>(Wu2, wh + WOFF_U2, 192, 32);

    // ---- encoder ----
    conv1_kernel<<<N0_/4, 256>>>(points0, neighbors0, features, kpoints, W1, f1);

    gather_mma_kernel<64,8><<<N1_/8, 256>>>(points1, points0, pools0, f1, kpoints, 0.5f, fk, N1_);
    gemm_tc<2,1,true,false,true,false><<<dim3(1,(N1_+127)/128), 256>>>(fk, wh+WOFF_W2, f2, N1_, 64, 960, nullptr, nullptr, 0, 0, nullptr, nullptr);

    gather_mma_kernel<64,8><<<N1_/8, 256>>>(points1, points1, neighbors1, f2, kpoints, 1.0f, fk, N1_);
    gemm_tc<2,2,true,false,true,false><<<dim3(1,(N1_+127)/128), 256>>>(fk, wh+WOFF_W3, f3, N1_, 128, 960, nullptr, nullptr, 0, 0, nullptr, nullptr);

    gather_mma_kernel<128,4><<<(N2_+3)/4, 128>>>(points2, points1, pools1, f3, kpoints, 1.0f, fk, N2_);
    gemm_tc<1,1,true,false,true,false><<<dim3(2,(N2_+63)/64), 256>>>(fk, wh+WOFF_W4, f4, N2_, 128, 1920, nullptr, nullptr, 0, 0, nullptr, nullptr);

    gather_mma_kernel<128,4><<<(N2_+3)/4, 128>>>(points2, points2, neighbors2, f4, kpoints, 2.0f, fk, N2_);
    gemm_tc<1,2,true,false,true,false><<<dim3(2,(N2_+63)/64), 256>>>(fk, wh+WOFF_W5, f5, N2_, 256, 1920, nullptr, nullptr, 0, 0, nullptr, nullptr);

    // ---- decoder (concat fused into GEMM A-load) ----
    gemm_tc<2,2,true,true,true,false><<<dim3(1,(N1_+127)/128), 256>>>(f5, wh+WOFF_U1, fu1, N1_, 128, 384,
                                                                      upsamples1, f3, 256, 128, nullptr, nullptr);
    init_gmax_kernel<<<1,1>>>();
    gemm_tc<2,1,false,true,false,true><<<dim3(1,(N0_+127)/128), 256>>>(fu1, wh+WOFF_U2, ff, N0_, 32, 192,
                                                                       upsamples0, f1, 128, 64, rowsum, gmaxp);

    // ---- detection head + outputs ----
    scores_kernel<<<(N0_ + 7)/8, 256>>>(neighbors0, ff, rowsum, out, out + (size_t)N0_*32);
}

// round 7
// speedup vs baseline: 3.3467x; 1.1441x over previous
#include <cuda_runtime.h>
#include <cuda_fp16.h>
#include <math.h>
#include <stdint.h>

#define N0_ 60000
#define N1_ 15000
#define N2_ 3750
#define K_  32
#define P_  15

// ---------------- intermediate buffers (device globals; no allocations) ----------
__device__ __align__(16) __half g_f1 [N0_*64];        // skip0
__device__ __align__(16) __half g_f2 [N1_*64];
__device__ __align__(16) __half g_f3 [N1_*128];       // skip1
__device__ __align__(16) __half g_f4 [N2_*128];
__device__ __align__(16) __half g_f5 [N2_*256];
__device__ __align__(16) __half g_fk [N1_*P_*64];     // reused by all gathers
__device__ __align__(16) __half g_fu1[N1_*128];
__device__ __align__(16) float  g_ff [N0_*32];
__device__ __align__(16) __half g_wh [976896];        // all transposed half weights
__device__ float g_rowsum[N0_];
__device__ int g_gmax;

#define WOFF_W2  0
#define WOFF_W3  61440
#define WOFF_W4  184320
#define WOFF_W5  430080
#define WOFF_U1  921600
#define WOFF_U2  970752

// ---------------- fused prep: all 6 weight transposes fp32[Kd][N]->half[N][Kd] ----
// All dims are multiples of 32 -> no bounds checks. Block 0 also resets g_gmax.
__global__ __launch_bounds__(256)
void prep_kernel(const float* __restrict__ W2, const float* __restrict__ W3,
                 const float* __restrict__ W4, const float* __restrict__ W5,
                 const float* __restrict__ Wu1, const float* __restrict__ Wu2,
                 __half* __restrict__ wh)
{
    __shared__ float tile[32][33];
    int b = blockIdx.x;
    if (b == 0 && threadIdx.x == 0) g_gmax = 0;
    const float* src; __half* dst; int Kd, N, gx;
    if      (b < 60)  { src=W2;  dst=wh+WOFF_W2; Kd=960;  N=64;  gx=30; }
    else if (b < 180) { src=W3;  dst=wh+WOFF_W3; Kd=960;  N=128; gx=30; b-=60; }
    else if (b < 420) { src=W4;  dst=wh+WOFF_W4; Kd=1920; N=128; gx=60; b-=180; }
    else if (b < 900) { src=W5;  dst=wh+WOFF_W5; Kd=1920; N=256; gx=60; b-=420; }
    else if (b < 948) { src=Wu1; dst=wh+WOFF_U1; Kd=384;  N=128; gx=12; b-=900; }
    else              { src=Wu2; dst=wh+WOFF_U2; Kd=192;  N=32;  gx=6;  b-=948; }
    int kb = (b % gx)*32, nb = (b / gx)*32;
    int tx = threadIdx.x & 31, ty = threadIdx.x >> 5;   // 32 x 8
    #pragma unroll
    for (int r = 0; r < 32; r += 8)
        tile[ty+r][tx] = src[(size_t)(kb+ty+r)*N + nb + tx];
    __syncthreads();
    #pragma unroll
    for (int r = 0; r < 32; r += 8)
        dst[(size_t)(nb+ty+r)*Kd + kb + tx] = __float2half(tile[tx][ty+r]);
}

// ---------------- layer 1: KPConv Cin=1 Cout=64 ----------------------------------
__global__ __launch_bounds__(256)
void conv1_kernel(const float* __restrict__ pts, const int* __restrict__ neigh,
                  const float* __restrict__ feats, const float* __restrict__ kp,
                  const float* __restrict__ W1, __half* __restrict__ out)
{
    const float extent = 0.5f;
    __shared__ float sdiff[4][K_][3];
    __shared__ float sfeat[4][K_];
    __shared__ float sinfl[4][K_*P_];
    __shared__ float sfk[4][P_];
    int pt = threadIdx.x >> 6;
    int t  = threadIdx.x & 63;
    int n  = blockIdx.x * 4 + pt;
    if (t < K_) {
        int idx = neigh[n*K_+t];
        float qx = pts[n*3+0], qy = pts[n*3+1], qz = pts[n*3+2];
        sdiff[pt][t][0] = pts[idx*3+0]-qx;
        sdiff[pt][t][1] = pts[idx*3+1]-qy;
        sdiff[pt][t][2] = pts[idx*3+2]-qz;
        sfeat[pt][t] = feats[idx];
    }
    __syncthreads();
    for (int i = t; i < K_*P_; i += 64) {
        int k = i / P_, p = i % P_;
        float dx = sdiff[pt][k][0] - kp[p*3+0]*extent;
        float dy = sdiff[pt][k][1] - kp[p*3+1]*extent;
        float dz = sdiff[pt][k][2] - kp[p*3+2]*extent;
        float dist = sqrtf(dx*dx+dy*dy+dz*dz);
        sinfl[pt][i] = fmaxf(0.f, 1.f - dist/extent);
    }
    __syncthreads();
    if (t < P_) {
        float acc = 0.f;
        #pragma unroll
        for (int k = 0; k < K_; k++) acc += sinfl[pt][k*P_+t]*sfeat[pt][k];
        sfk[pt][t] = acc;
    }
    __syncthreads();
    float acc = 0.f;
    #pragma unroll
    for (int p = 0; p < P_; p++) acc += sfk[pt][p]*W1[p*64+t];
    out[n*64+t] = __float2half(acc > 0.f ? acc : 0.1f*acc);
}

// ---------------- tensor-core gather (unchanged, verified R6) --------------------
__device__ __forceinline__ void ldsm4t(uint32_t& r0, uint32_t& r1, uint32_t& r2,
                                       uint32_t& r3, uint32_t addr)
{
    asm volatile("ldmatrix.sync.aligned.m8n8.x4.trans.shared.b16 {%0,%1,%2,%3}, [%4];"
                 : "=r"(r0), "=r"(r1), "=r"(r2), "=r"(r3) : "r"(addr));
}

template<int CIN, int WPB>
__global__ __launch_bounds__(32*WPB)
void gather_mma_kernel(const float* __restrict__ qpts, const float* __restrict__ spts,
                       const int* __restrict__ neigh, const __half* __restrict__ feats,
                       const float* __restrict__ kp, float extent,
                       __half* __restrict__ fk, int Npts)
{
    constexpr int STR = CIN + 8;
    constexpr int MT  = CIN / 16;
    __shared__ __half nf[WPB][32][STR];
    __shared__ float  sdiff[WPB][32][4];
    __shared__ int    sidx[WPB][32];

    const int w    = threadIdx.x >> 5;
    const int lane = threadIdx.x & 31;
    const int n    = blockIdx.x * WPB + w;
    if (n >= Npts) return;
    const int g = lane >> 2, t4 = lane & 3;

    {
        int idx = neigh[n*K_ + lane];
        sidx[w][lane] = idx;
        float qx = qpts[n*3+0], qy = qpts[n*3+1], qz = qpts[n*3+2];
        sdiff[w][lane][0] = spts[idx*3+0]-qx;
        sdiff[w][lane][1] = spts[idx*3+1]-qy;
        sdiff[w][lane][2] = spts[idx*3+2]-qz;
    }
    __syncwarp();

    if (CIN == 64) {
        #pragma unroll
        for (int r = 0; r < 8; r++) {
            int row = r*4 + (lane>>3);
            int ch  = (lane&7)*8;
            uint4 v = *(const uint4*)(feats + (size_t)sidx[w][row]*CIN + ch);
            *(uint4*)&nf[w][row][ch] = v;
        }
    } else {
        #pragma unroll
        for (int r = 0; r < 16; r++) {
            int row = r*2 + (lane>>4);
            int ch  = (lane&15)*8;
            uint4 v = *(const uint4*)(feats + (size_t)sidx[w][row]*CIN + ch);
            *(uint4*)&nf[w][row][ch] = v;
        }
    }

    const float inv_e = 1.0f / extent;
    uint32_t bfr[2][2][2];
    #pragma unroll
    for (int nt = 0; nt < 2; nt++) {
        int p = nt*8 + g;
        bool pv = p < P_;
        float px = 0.f, py = 0.f, pz = 0.f;
        if (pv) {
            px = kp[p*3+0]*extent; py = kp[p*3+1]*extent; pz = kp[p*3+2]*extent;
        }
        #pragma unroll
        for (int ks = 0; ks < 2; ks++) {
            int kb = ks*16 + 2*t4;
            float v[4];
            #pragma unroll
            for (int j = 0; j < 4; j++) {
                int k = kb + (j>>1)*8 + (j&1);
                float dx = sdiff[w][k][0]-px;
                float dy = sdiff[w][k][1]-py;
                float dz = sdiff[w][k][2]-pz;
                float d = sqrtf(dx*dx+dy*dy+dz*dz);
                v[j] = pv ? fmaxf(0.f, 1.f - d*inv_e) : 0.f;
            }
            __half2 h0 = __floats2half2_rn(v[0], v[1]);
            __half2 h1 = __floats2half2_rn(v[2], v[3]);
            bfr[nt][ks][0] = *reinterpret_cast<uint32_t*>(&h0);
            bfr[nt][ks][1] = *reinterpret_cast<uint32_t*>(&h1);
        }
    }
    __syncwarp();

    float d[MT][2][4];
    #pragma unroll
    for (int mt = 0; mt < MT; mt++)
        #pragma unroll
        for (int nt = 0; nt < 2; nt++) {
            d[mt][nt][0]=0.f; d[mt][nt][1]=0.f; d[mt][nt][2]=0.f; d[mt][nt][3]=0.f;
        }
    uint32_t nf_base = (uint32_t)__cvta_generic_to_shared(&nf[w][0][0]);
    const int grp = lane >> 3, jj = lane & 7;
    #pragma unroll
    for (int mt = 0; mt < MT; mt++) {
        #pragma unroll
        for (int ks = 0; ks < 2; ks++) {
            int krow = ks*16 + ((grp & 2) ? 8 : 0) + jj;
            int mcol = mt*16 + ((grp & 1) ? 8 : 0);
            uint32_t addr = nf_base + (uint32_t)(krow*STR + mcol)*2u;
            uint32_t a0,a1,a2,a3;
            ldsm4t(a0,a1,a2,a3, addr);
            #pragma unroll
            for (int nt = 0; nt < 2; nt++)
                asm volatile(
                    "mma.sync.aligned.m16n8k16.row.col.f32.f16.f16.f32 "
                    "{%0,%1,%2,%3},{%4,%5,%6,%7},{%8,%9},{%0,%1,%2,%3};\n"
                    : "+f"(d[mt][nt][0]), "+f"(d[mt][nt][1]),
                      "+f"(d[mt][nt][2]), "+f"(d[mt][nt][3])
                    : "r"(a0), "r"(a1), "r"(a2), "r"(a3),
                      "r"(bfr[nt][ks][0]), "r"(bfr[nt][ks][1]));
        }
    }
    __syncwarp();

    #pragma unroll
    for (int mt = 0; mt < MT; mt++) {
        int c = mt*16 + g;
        #pragma unroll
        for (int nt = 0; nt < 2; nt++) {
            int p0 = nt*8 + 2*t4;
            nf[w][p0  ][c  ] = __float2half(d[mt][nt][0]);
            nf[w][p0+1][c  ] = __float2half(d[mt][nt][1]);
            nf[w][p0  ][c+8] = __float2half(d[mt][nt][2]);
            nf[w][p0+1][c+8] = __float2half(d[mt][nt][3]);
        }
    }
    __syncwarp();
    constexpr int CH = P_ * CIN / 8;
    #pragma unroll
    for (int cid = lane; cid < CH; cid += 32) {
        int p = cid / (CIN/8), cc = cid % (CIN/8);
        uint4 v = *(const uint4*)&nf[w][p][cc*8];
        *(uint4*)(fk + (size_t)n*(P_*CIN) + cid*8) = v;
    }
}

// ================= fp16 tensor-core GEMM: 3-stage cp.async, 1 sync/iter ==========
__device__ __forceinline__ void cpasync16(uint32_t dst, const void* src, bool valid) {
    int sz = valid ? 16 : 0;
    asm volatile("cp.async.cg.shared.global [%0], [%1], 16, %2;\n"
                 :: "r"(dst), "l"(src), "r"(sz));
}

template<int MF, int NF, bool LEAKY, bool CAT, bool OUTHALF, bool STATS>
__global__ __launch_bounds__(256)
void gemm_tc(const __half* __restrict__ A, const __half* __restrict__ Bt,
             void* __restrict__ Cv, int M, int N, int Kd,
             const int* __restrict__ upidx, const __half* __restrict__ Askip,
             int c_up, int c_skip, float* __restrict__ rowsum, int* __restrict__ gmaxp)
{
    constexpr int BM = MF * 64, BN = NF * 64;
    extern __shared__ __align__(16) __half dynsm[];
    __half (*As)[BM][40] = reinterpret_cast<__half (*)[BM][40]>(dynsm);
    __half (*Bs)[BN][40] = reinterpret_cast<__half (*)[BN][40]>(dynsm + 3*BM*40);
    __shared__ float swm[8];

    const int bm = blockIdx.y * BM, bn = blockIdx.x * BN;
    const int tid  = threadIdx.x;
    const int warp = tid >> 5, lane = tid & 31;
    const int wm = warp >> 1, wn = warp & 1;
    const int g  = lane >> 2, tg = lane & 3;

    float c[MF][4*NF][4];
    #pragma unroll
    for (int i = 0; i < MF; i++)
        #pragma unroll
        for (int j = 0; j < 4*NF; j++) {
            c[i][j][0]=0.f; c[i][j][1]=0.f; c[i][j][2]=0.f; c[i][j][3]=0.f;
        }

    const int ar = tid >> 2;
    const int ac = (tid & 3) * 8;

    int ridx[MF];
    if (CAT) {
        #pragma unroll
        for (int i = 0; i < MF; i++) {
            int r = bm + ar + i * 64;
            ridx[i] = (r < M) ? upidx[r] : 0;
        }
    }

    const int nk = Kd >> 5;

    auto issue = [&](int s, int k0) {
        #pragma unroll
        for (int i = 0; i < MF; i++) {
            int r = ar + i * 64;
            bool v = (bm + r) < M;
            const __half* src;
            if (CAT) {
                int kc = k0 + ac;
                src = (kc < c_up) ? (A + (size_t)ridx[i] * c_up + kc)
                                  : (Askip + (size_t)(bm + r) * c_skip + (kc - c_up));
                if (!v) src = A;
            } else {
                src = v ? (A + (size_t)(bm + r) * Kd + k0 + ac) : A;
            }
            cpasync16((uint32_t)__cvta_generic_to_shared(&As[s][r][ac]), src, v);
        }
        #pragma unroll
        for (int j = 0; j < NF; j++) {
            int nrow = ar + j * 64;
            bool v = (bn + nrow) < N;
            const __half* srcb = v ? (Bt + (size_t)(bn + nrow) * Kd + k0 + ac) : Bt;
            cpasync16((uint32_t)__cvta_generic_to_shared(&Bs[s][nrow][ac]), srcb, v);
        }
        asm volatile("cp.async.commit_group;\n");
    };

    auto compute = [&](int s) {
        #pragma unroll
        for (int k0 = 0; k0 < 32; k0 += 16) {
            uint32_t a[MF][4], bf[4*NF][2];
            #pragma unroll
            for (int i = 0; i < MF; i++) {
                int r = wm * MF * 16 + i * 16 + g;
                a[i][0] = *(const uint32_t*)&As[s][r    ][k0 + 2*tg    ];
                a[i][1] = *(const uint32_t*)&As[s][r + 8][k0 + 2*tg    ];
                a[i][2] = *(const uint32_t*)&As[s][r    ][k0 + 2*tg + 8];
                a[i][3] = *(const uint32_t*)&As[s][r + 8][k0 + 2*tg + 8];
            }
            #pragma unroll
            for (int j = 0; j < 4*NF; j++) {
                int col = wn * NF * 32 + j * 8 + g;
                bf[j][0] = *(const uint32_t*)&Bs[s][col][k0 + 2*tg    ];
                bf[j][1] = *(const uint32_t*)&Bs[s][col][k0 + 2*tg + 8];
            }
            #pragma unroll
            for (int i = 0; i < MF; i++)
                #pragma unroll
                for (int j = 0; j < 4*NF; j++)
                    asm volatile(
                        "mma.sync.aligned.m16n8k16.row.col.f32.f16.f16.f32 "
                        "{%0,%1,%2,%3},{%4,%5,%6,%7},{%8,%9},{%0,%1,%2,%3};\n"
                        : "+f"(c[i][j][0]), "+f"(c[i][j][1]),
                          "+f"(c[i][j][2]), "+f"(c[i][j][3])
                        : "r"(a[i][0]), "r"(a[i][1]), "r"(a[i][2]), "r"(a[i][3]),
                          "r"(bf[j][0]), "r"(bf[j][1]));
        }
    };

    // 3-stage pipeline, one sync per iter, uniform one commit per iter.
    issue(0, 0);
    issue(1, 32);
    int st = 0;
    for (int kt = 0; kt < nk; kt++) {
        asm volatile("cp.async.wait_group 1;\n");
        __syncthreads();
        compute(st);
        int nx = kt + 2;
        int ws = st + 2; if (ws >= 3) ws -= 3;
        if (nx < nk) issue(ws, nx << 5);
        else asm volatile("cp.async.commit_group;\n");
        if (++st == 3) st = 0;
    }

    __half* Ch = (__half*)Cv;
    float*  Cf = (float*)Cv;
    #pragma unroll
    for (int i = 0; i < MF; i++) {
        int r0 = bm + wm * MF * 16 + i * 16 + g;
        #pragma unroll
        for (int j = 0; j < 4*NF; j++) {
            int col = bn + wn * NF * 32 + j * 8 + 2 * tg;
            if (col < N) {
                if (r0 < M) {
                    float v0 = c[i][j][0], v1 = c[i][j][1];
                    if (LEAKY) { v0 = v0 > 0.f ? v0 : 0.1f*v0; v1 = v1 > 0.f ? v1 : 0.1f*v1; }
                    if (OUTHALF) *(__half2*)&Ch[(size_t)r0 * N + col] = __floats2half2_rn(v0, v1);
                    else { Cf[(size_t)r0 * N + col] = v0; Cf[(size_t)r0 * N + col + 1] = v1; }
                }
                if (r0 + 8 < M) {
                    float v2 = c[i][j][2], v3 = c[i][j][3];
                    if (LEAKY) { v2 = v2 > 0.f ? v2 : 0.1f*v2; v3 = v3 > 0.f ? v3 : 0.1f*v3; }
                    if (OUTHALF) *(__half2*)&Ch[(size_t)(r0+8) * N + col] = __floats2half2_rn(v2, v3);
                    else { Cf[(size_t)(r0+8) * N + col] = v2; Cf[(size_t)(r0+8) * N + col + 1] = v3; }
                }
            }
        }
    }

    if (STATS) {
        float wmax = 0.f;
        if (wn == 0) {
            #pragma unroll
            for (int i = 0; i < MF; i++) {
                float sl = 0.f, sh = 0.f, ml = 0.f, mh = 0.f;
                #pragma unroll
                for (int j = 0; j < 4*NF; j++) {
                    sl += c[i][j][0] + c[i][j][1];
                    sh += c[i][j][2] + c[i][j][3];
                    ml = fmaxf(ml, fmaxf(c[i][j][0], c[i][j][1]));
                    mh = fmaxf(mh, fmaxf(c[i][j][2], c[i][j][3]));
                }
                sl += __shfl_xor_sync(0xffffffffu, sl, 1);
                sl += __shfl_xor_sync(0xffffffffu, sl, 2);
                sh += __shfl_xor_sync(0xffffffffu, sh, 1);
                sh += __shfl_xor_sync(0xffffffffu, sh, 2);
                ml = fmaxf(ml, __shfl_xor_sync(0xffffffffu, ml, 1));
                ml = fmaxf(ml, __shfl_xor_sync(0xffffffffu, ml, 2));
                mh = fmaxf(mh, __shfl_xor_sync(0xffffffffu, mh, 1));
                mh = fmaxf(mh, __shfl_xor_sync(0xffffffffu, mh, 2));
                int r0 = bm + wm * MF * 16 + i * 16 + g;
                if (tg == 0) {
                    if (r0 < M)     rowsum[r0]     = sl;
                    if (r0 + 8 < M) rowsum[r0 + 8] = sh;
                }
                wmax = fmaxf(wmax, fmaxf(ml, mh));
            }
        }
        #pragma unroll
        for (int o = 16; o; o >>= 1)
            wmax = fmaxf(wmax, __shfl_xor_sync(0xffffffffu, wmax, o));
        if (lane == 0) swm[warp] = wmax;
        __syncthreads();
        if (tid == 0) {
            float bmv = swm[0];
            #pragma unroll
            for (int ww = 1; ww < 8; ww++) bmv = fmaxf(bmv, swm[ww]);
            atomicMax(gmaxp, __float_as_int(fmaxf(bmv, 0.f)));
        }
    }
}

// ---------------- detection head: float4 neighbor accumulation -------------------
__global__ void scores_kernel(const int* __restrict__ neigh, const float* __restrict__ ff,
                              const float* __restrict__ rowsum,
                              float* __restrict__ out_fnorm, float* __restrict__ out_scores)
{
    int warp = (blockIdx.x*blockDim.x + threadIdx.x) >> 5;
    int lane = threadIdx.x & 31;
    if (warp >= N0_) return;
    float fraw = ff[(size_t)warp*32 + lane];
    float s2 = fraw*fraw;
    #pragma unroll
    for (int o = 16; o; o >>= 1) s2 += __shfl_xor_sync(0xffffffffu, s2, o);
    float nrm = fmaxf(sqrtf(s2), 1e-12f);
    out_fnorm[(size_t)warp*32 + lane] = fraw / nrm;

    float inv = 1.0f / (__int_as_float(g_gmax) + 1e-6f);
    int myidx = neigh[(size_t)warp*32 + lane];

    int nz = (rowsum[myidx] != 0.f) ? 1 : 0;
    #pragma unroll
    for (int o = 16; o; o >>= 1) nz += __shfl_xor_sync(0xffffffffu, nz, o);
    float nnumf = (float)(nz < 1 ? 1 : nz);

    // lane = (channel-quad c4, neighbor-subset kg): 8 LDG.128 cover all 32 rows.
    const int c4 = lane & 7, kg = lane >> 3;
    float4 sum4 = make_float4(0.f,0.f,0.f,0.f);
    float4 max4 = make_float4(-1e30f,-1e30f,-1e30f,-1e30f);
    #pragma unroll
    for (int i = 0; i < 8; i++) {
        int idx = __shfl_sync(0xffffffffu, myidx, i*4 + kg);
        float4 v = *(const float4*)(ff + (size_t)idx*32 + c4*4);
        sum4.x += v.x; sum4.y += v.y; sum4.z += v.z; sum4.w += v.w;
        max4.x = fmaxf(max4.x, v.x); max4.y = fmaxf(max4.y, v.y);
        max4.z = fmaxf(max4.z, v.z); max4.w = fmaxf(max4.w, v.w);
    }
    #pragma unroll
    for (int o = 8; o <= 16; o <<= 1) {
        sum4.x += __shfl_xor_sync(0xffffffffu, sum4.x, o);
        sum4.y += __shfl_xor_sync(0xffffffffu, sum4.y, o);
        sum4.z += __shfl_xor_sync(0xffffffffu, sum4.z, o);
        sum4.w += __shfl_xor_sync(0xffffffffu, sum4.w, o);
        max4.x = fmaxf(max4.x, __shfl_xor_sync(0xffffffffu, max4.x, o));
        max4.y = fmaxf(max4.y, __shfl_xor_sync(0xffffffffu, max4.y, o));
        max4.z = fmaxf(max4.z, __shfl_xor_sync(0xffffffffu, max4.z, o));
        max4.w = fmaxf(max4.w, __shfl_xor_sync(0xffffffffu, max4.w, o));
    }
    // redistribute: lane needs channel==lane -> source lane (lane>>2) component (lane&3)
    int src = lane >> 2;
    float sx = __shfl_sync(0xffffffffu, sum4.x, src);
    float sy = __shfl_sync(0xffffffffu, sum4.y, src);
    float sz = __shfl_sync(0xffffffffu, sum4.z, src);
    float sw = __shfl_sync(0xffffffffu, sum4.w, src);
    float mx = __shfl_sync(0xffffffffu, max4.x, src);
    float my = __shfl_sync(0xffffffffu, max4.y, src);
    float mz = __shfl_sync(0xffffffffu, max4.z, src);
    float mw = __shfl_sync(0xffffffffu, max4.w, src);
    int comp = lane & 3;
    float msum = (comp == 0) ? sx : (comp == 1) ? sy : (comp == 2) ? sz : sw;
    float mraw = (comp == 0) ? mx : (comp == 1) ? my : (comp == 2) ? mz : mw;

    float f = fraw * inv;
    float mean = msum * inv / nnumf;
    float nmax = mraw * inv;
    float x = f - mean;
    float lms = fmaxf(x, 0.f) + log1pf(expf(-fabsf(x)));
    float dmax = f;
    #pragma unroll
    for (int o = 16; o; o >>= 1) dmax = fmaxf(dmax, __shfl_xor_sync(0xffffffffu, dmax, o));
    float sc = lms * f / (1e-6f + dmax);
    float det = (f == nmax) ? 1.f : 0.f;
    #pragma unroll
    for (int o = 16; o; o >>= 1) {
        sc  = fmaxf(sc,  __shfl_xor_sync(0xffffffffu, sc, o));
        det = fmaxf(det, __shfl_xor_sync(0xffffffffu, det, o));
    }
    if (lane == 0) out_scores[warp] = sc * det;
}

// ---------------- launch ----------------------------------------------------------
extern "C" void kernel_launch(void* const* d_in, const int* in_sizes, int n_in,
                              void* d_out, int out_size)
{
    const float* features   = (const float*)d_in[0];
    const float* points0    = (const float*)d_in[1];
    const float* points1    = (const float*)d_in[2];
    const float* points2    = (const float*)d_in[3];
    const int*   neighbors0 = (const int*)d_in[4];
    const int*   neighbors1 = (const int*)d_in[5];
    const int*   neighbors2 = (const int*)d_in[6];
    const int*   pools0     = (const int*)d_in[7];
    const int*   pools1     = (const int*)d_in[8];
    const int*   upsamples0 = (const int*)d_in[9];
    const int*   upsamples1 = (const int*)d_in[10];
    const float* kpoints    = (const float*)d_in[11];
    const float* W1  = (const float*)d_in[12];
    const float* W2  = (const float*)d_in[13];
    const float* W3  = (const float*)d_in[14];
    const float* W4  = (const float*)d_in[15];
    const float* W5  = (const float*)d_in[16];
    const float* Wu1 = (const float*)d_in[17];
    const float* Wu2 = (const float*)d_in[18];
    float* out = (float*)d_out;

    __half *f1,*f2,*f3,*f4,*f5,*fk,*fu1,*wh;
    float *ff,*rowsum;
    int *gmaxp;
    cudaGetSymbolAddress((void**)&f1,  g_f1);
    cudaGetSymbolAddress((void**)&f2,  g_f2);
    cudaGetSymbolAddress((void**)&f3,  g_f3);
    cudaGetSymbolAddress((void**)&f4,  g_f4);
    cudaGetSymbolAddress((void**)&f5,  g_f5);
    cudaGetSymbolAddress((void**)&fk,  g_fk);
    cudaGetSymbolAddress((void**)&fu1, g_fu1);
    cudaGetSymbolAddress((void**)&wh,  g_wh);
    cudaGetSymbolAddress((void**)&ff,  g_ff);
    cudaGetSymbolAddress((void**)&rowsum, g_rowsum);
    cudaGetSymbolAddress((void**)&gmaxp,  g_gmax);

    // dynamic smem: 3 stages * (BM+BN)*40 halfs * 2B
    const int sm21 = 3*(128+ 64)*40*2;   // 46080
    const int sm22 = 3*(128+128)*40*2;   // 61440
    const int sm11 = 3*( 64+ 64)*40*2;   // 30720
    const int sm12 = 3*( 64+128)*40*2;   // 46080
    cudaFuncSetAttribute(gemm_tc<2,1,true,false,true,false>,  cudaFuncAttributeMaxDynamicSharedMemorySize, sm21);
    cudaFuncSetAttribute(gemm_tc<2,2,true,false,true,false>,  cudaFuncAttributeMaxDynamicSharedMemorySize, sm22);
    cudaFuncSetAttribute(gemm_tc<1,1,true,false,true,false>,  cudaFuncAttributeMaxDynamicSharedMemorySize, sm11);
    cudaFuncSetAttribute(gemm_tc<1,2,true,false,true,false>,  cudaFuncAttributeMaxDynamicSharedMemorySize, sm12);
    cudaFuncSetAttribute(gemm_tc<2,2,true,true,true,false>,   cudaFuncAttributeMaxDynamicSharedMemorySize, sm22);
    cudaFuncSetAttribute(gemm_tc<2,1,false,true,false,true>,  cudaFuncAttributeMaxDynamicSharedMemorySize, sm21);

    // ---- prep (all weight transposes + gmax reset, one launch) ----
    prep_kernel<<<954, 256>>>(W2, W3, W4, W5, Wu1, Wu2, wh);

    // ---- encoder ----
    conv1_kernel<<<N0_/4, 256>>>(points0, neighbors0, features, kpoints, W1, f1);

    gather_mma_kernel<64,8><<<N1_/8, 256>>>(points1, points0, pools0, f1, kpoints, 0.5f, fk, N1_);
    gemm_tc<2,1,true,false,true,false><<<dim3(1,(N1_+127)/128), 256, sm21>>>(fk, wh+WOFF_W2, f2, N1_, 64, 960, nullptr, nullptr, 0, 0, nullptr, nullptr);

    gather_mma_kernel<64,8><<<N1_/8, 256>>>(points1, points1, neighbors1, f2, kpoints, 1.0f, fk, N1_);
    gemm_tc<2,2,true,false,true,false><<<dim3(1,(N1_+127)/128), 256, sm22>>>(fk, wh+WOFF_W3, f3, N1_, 128, 960, nullptr, nullptr, 0, 0, nullptr, nullptr);

    gather_mma_kernel<128,4><<<(N2_+3)/4, 128>>>(points2, points1, pools1, f3, kpoints, 1.0f, fk, N2_);
    gemm_tc<1,1,true,false,true,false><<<dim3(2,(N2_+63)/64), 256, sm11>>>(fk, wh+WOFF_W4, f4, N2_, 128, 1920, nullptr, nullptr, 0, 0, nullptr, nullptr);

    gather_mma_kernel<128,4><<<(N2_+3)/4, 128>>>(points2, points2, neighbors2, f4, kpoints, 2.0f, fk, N2_);
    gemm_tc<1,2,true,false,true,false><<<dim3(2,(N2_+63)/64), 256, sm12>>>(fk, wh+WOFF_W5, f5, N2_, 256, 1920, nullptr, nullptr, 0, 0, nullptr, nullptr);

    // ---- decoder (concat fused into GEMM A-load) ----
    gemm_tc<2,2,true,true,true,false><<<dim3(1,(N1_+127)/128), 256, sm22>>>(f5, wh+WOFF_U1, fu1, N1_, 128, 384,
                                                                            upsamples1, f3, 256, 128, nullptr, nullptr);
    gemm_tc<2,1,false,true,false,true><<<dim3(1,(N0_+127)/128), 256, sm21>>>(fu1, wh+WOFF_U2, ff, N0_, 32, 192,
                                                                             upsamples0, f1, 128, 64, rowsum, gmaxp);

    // ---- detection head + outputs ----
    scores_kernel<<<(N0_ + 7)/8, 256>>>(neighbors0, ff, rowsum, out, out + (size_t)N0_*32);
}